// round 12
// baseline (speedup 1.0000x reference)
#include <cuda_runtime.h>
#include <cuda_bf16.h>
#include <cstdint>

// ---------------------------------------------------------------------------
// Problem constants
// ---------------------------------------------------------------------------
#define S_   128
#define B_   128
#define C_   256
#define E_   256
#define D_   512
#define EMB_ 256
#define V_   10000
#define T_   32
#define FEAT_ (D_ + 2*E_ + EMB_)   // 1280
#define VPAD_ 10240

typedef unsigned long long ull;

// ---------------------------------------------------------------------------
// Scratch (__device__ globals; allocation-free)
// ---------------------------------------------------------------------------
__device__ float g_pre[S_ * B_ * 512];               // (S*B, 512) = [f|b]
__device__ float g_WhhT[2 * E_ * E_];
__device__ float g_enc_out[S_ * B_ * 2 * E_];
__device__ float g_enc_part[S_ * B_ * D_];
__device__ float g_hcat[B_ * 2 * E_];
__device__ float g_h[B_ * D_];
__device__ float g_gi_emb[T_ * B_ * 3 * D_];
__device__ float g_feat[T_ * B_ * FEAT_];
__device__ float g_p1[2 * B_ * 2048];                // split-K partials (gh|q)
__device__ float g_p2[2 * B_ * 1536];                // split-K partials (gi)
__device__ float g_bpre[512];

// factored split-bf16 operands: per row, K/32 blocks of [h(32)|l(32)]
__device__ __align__(16) __nv_bfloat16 g_A2[(size_t)(T_ * B_) * 2560];
__device__ __align__(16) __nv_bfloat16 g_B2[(size_t)VPAD_ * 2560];
__device__ __align__(16) __nv_bfloat16 gA2_src[(size_t)16384 * 512];
__device__ __align__(16) __nv_bfloat16 gB2_pre[512 * 512];
__device__ __align__(16) __nv_bfloat16 gA2_enc[(size_t)16384 * 1024];
__device__ __align__(16) __nv_bfloat16 gB2_attn[512 * 1024];
__device__ __align__(16) __nv_bfloat16 gA2_emb[4096 * 512];
__device__ __align__(16) __nv_bfloat16 gB2_wih[1536 * 512];

// ---------------------------------------------------------------------------
// helpers
// ---------------------------------------------------------------------------
__device__ __forceinline__ ull pk2(float lo, float hi) {
    ull r;
    asm("mov.b64 %0, {%1, %2};" : "=l"(r) : "f"(lo), "f"(hi));
    return r;
}
__device__ __forceinline__ void upk2(ull v, float& lo, float& hi) {
    asm("mov.b64 {%0, %1}, %2;" : "=f"(lo), "=f"(hi) : "l"(v));
}
__device__ __forceinline__ void fma2(ull& d, ull a, ull b) {
    asm("fma.rn.f32x2 %0, %1, %2, %0;" : "+l"(d) : "l"(a), "l"(b));
}
__device__ __forceinline__ uint32_t smem_u32(const void* p) {
    uint32_t a;
    asm("{ .reg .u64 t; cvta.to.shared.u64 t, %1; cvt.u32.u64 %0, t; }"
        : "=r"(a) : "l"(p));
    return a;
}

// ---------------------------------------------------------------------------
// split fp32 -> factored bf16 [h(32)|l(32)] per 32-element K block.
// ---------------------------------------------------------------------------
__global__ __launch_bounds__(256) void split2_k(
    const float* __restrict__ src, int lda, int Kf, int realRows,
    __nv_bfloat16* __restrict__ dst)
{
    const int k = blockIdx.x * 256 + threadIdx.x;
    const int r = blockIdx.y;
    float x = (r < realRows) ? src[(size_t)r * lda + k] : 0.f;
    __nv_bfloat16 h = __float2bfloat16(x);
    __nv_bfloat16 l = __float2bfloat16(x - __bfloat162float(h));
    size_t base = (size_t)r * 2 * Kf + (size_t)(k >> 5) * 64 + (k & 31);
    dst[base] = h;
    dst[base + 32] = l;
}

__global__ __launch_bounds__(256) void splitB2_pre_k(
    const float* __restrict__ Wf, const float* __restrict__ Wb)
{
    const int k = threadIdx.x;
    const int r = blockIdx.y;
    const float* W = (r < 256) ? Wf : Wb;
    float x = W[(size_t)(r & 255) * 256 + k];
    __nv_bfloat16 h = __float2bfloat16(x);
    __nv_bfloat16 l = __float2bfloat16(x - __bfloat162float(h));
    size_t base = (size_t)r * 512 + (size_t)(k >> 5) * 64 + (k & 31);
    gB2_pre[base] = h;
    gB2_pre[base + 32] = l;
}

__global__ void cat_bias_k(const float* __restrict__ a, const float* __restrict__ b)
{
    int i = blockIdx.x * 256 + threadIdx.x;
    g_bpre[i] = (i < 256) ? a[i] : b[i - 256];
}

// ---------------------------------------------------------------------------
// Factored split-bf16 HMMA GEMM (R9-proven config, interleaved LDSM/MMA):
//   C[row(m_base + m), n] = sum A*B + bias, fp32-split-bf16 3-product.
// CTA 128x128, 256 threads, 8 warps of 64x32, 3-stage cp.async pipeline.
// flags: bit0 = tanh, bit1 = (b,t) scatter for logits.
// ---------------------------------------------------------------------------
#define L3 72                          // bf16 per smem row (144 B)
#define HSTG_A (128 * L3 * 2)          // 18432 B
#define HSTG   (2 * HSTG_A)            // 36864 B (A + B)
#define HMMA_SMEM (3 * HSTG)           // 110592 B

__global__ __launch_bounds__(256, 2) void gemm_hmma(
    const __nv_bfloat16* __restrict__ A2, const __nv_bfloat16* __restrict__ B2,
    const float* __restrict__ bias, float* __restrict__ C,
    int ldc, int N, int NCH, int flags, int m_base)
{
    extern __shared__ __align__(16) char sm[];
    const uint32_t sbase = smem_u32(sm);
    const int tid = threadIdx.x, wid = tid >> 5, lane = tid & 31;
    const int m0 = m_base + blockIdx.y * 128, n0 = blockIdx.x * 128;
    const size_t ldk = (size_t)NCH * 64;

    const int lrow = tid >> 3;
    const int lcg  = tid & 7;
    const __nv_bfloat16* gA = A2 + (size_t)m0 * ldk;
    const __nv_bfloat16* gB = B2 + (size_t)n0 * ldk;

    float acc[4][4][4];
#pragma unroll
    for (int a = 0; a < 4; a++)
#pragma unroll
        for (int b = 0; b < 4; b++)
#pragma unroll
            for (int c = 0; c < 4; c++) acc[a][b][c] = 0.f;

    const int wr = wid >> 2, wc = wid & 3;
    const int wm = wr * 64, wn = wc * 32;

    auto issue_stage = [&](int c, int buf) {
        uint32_t sa = sbase + buf * HSTG;
        uint32_t sb = sa + HSTG_A;
        size_t kof = (size_t)c * 64 + lcg * 8;
#pragma unroll
        for (int i = 0; i < 4; i++) {
            int row = lrow + i * 32;
            uint32_t da = sa + (uint32_t)(row * L3 + lcg * 8) * 2;
            const void* pa = gA + (size_t)row * ldk + kof;
            asm volatile("cp.async.cg.shared.global [%0], [%1], 16;"
                         :: "r"(da), "l"(pa));
            uint32_t db = sb + (uint32_t)(row * L3 + lcg * 8) * 2;
            const void* pb = gB + (size_t)row * ldk + kof;
            asm volatile("cp.async.cg.shared.global [%0], [%1], 16;"
                         :: "r"(db), "l"(pb));
        }
        asm volatile("cp.async.commit_group;" ::: "memory");
    };

    issue_stage(0, 0);
    issue_stage(1, 1);

    int buf = 0;
    for (int c = 0; c < NCH; c++) {
        if (c + 2 < NCH) {
            int nb = buf + 2; if (nb >= 3) nb -= 3;
            issue_stage(c + 2, nb);
            asm volatile("cp.async.wait_group 2;" ::: "memory");
        } else if (c + 1 < NCH) {
            asm volatile("cp.async.wait_group 1;" ::: "memory");
        } else {
            asm volatile("cp.async.wait_group 0;" ::: "memory");
        }
        __syncthreads();

        const uint32_t sa  = sbase + buf * HSTG;
        const uint32_t sbm = sa + HSTG_A;

#pragma unroll
        for (int ks = 0; ks < 2; ks++) {
            const int acol = ks * 16 + ((lane >> 4) << 3);
            const int bcol = ks * 16 + ((lane & 8) ? 8 : 0);
            uint32_t bh[2][4], bl[2][4];
#pragma unroll
            for (int j = 0; j < 2; j++) {
                int row = wn + j * 16 + (lane & 7) + ((lane & 16) ? 8 : 0);
                uint32_t ad = sbm + (uint32_t)(row * L3 + bcol) * 2;
                asm volatile(
                    "ldmatrix.sync.aligned.m8n8.x4.shared.b16 {%0,%1,%2,%3}, [%4];"
                    : "=r"(bh[j][0]), "=r"(bh[j][1]),
                      "=r"(bh[j][2]), "=r"(bh[j][3])
                    : "r"(ad));
                asm volatile(
                    "ldmatrix.sync.aligned.m8n8.x4.shared.b16 {%0,%1,%2,%3}, [%4];"
                    : "=r"(bl[j][0]), "=r"(bl[j][1]),
                      "=r"(bl[j][2]), "=r"(bl[j][3])
                    : "r"(ad + 64));
            }
#pragma unroll
            for (int mt = 0; mt < 4; mt++) {
                int row = wm + mt * 16 + (lane & 15);
                uint32_t ah[4], al[4];
                uint32_t aad = sa + (uint32_t)(row * L3 + acol) * 2;
                asm volatile(
                    "ldmatrix.sync.aligned.m8n8.x4.shared.b16 {%0,%1,%2,%3}, [%4];"
                    : "=r"(ah[0]), "=r"(ah[1]), "=r"(ah[2]), "=r"(ah[3])
                    : "r"(aad));
                asm volatile(
                    "ldmatrix.sync.aligned.m8n8.x4.shared.b16 {%0,%1,%2,%3}, [%4];"
                    : "=r"(al[0]), "=r"(al[1]), "=r"(al[2]), "=r"(al[3])
                    : "r"(aad + 64));
#pragma unroll
                for (int nt = 0; nt < 4; nt++) {
                    uint32_t b0 = bh[nt >> 1][(nt & 1) * 2 + 0];
                    uint32_t b1 = bh[nt >> 1][(nt & 1) * 2 + 1];
                    uint32_t c0 = bl[nt >> 1][(nt & 1) * 2 + 0];
                    uint32_t c1 = bl[nt >> 1][(nt & 1) * 2 + 1];
                    asm volatile(
                        "mma.sync.aligned.m16n8k16.row.col.f32.bf16.bf16.f32 "
                        "{%0,%1,%2,%3}, {%4,%5,%6,%7}, {%8,%9}, {%0,%1,%2,%3};"
                        : "+f"(acc[mt][nt][0]), "+f"(acc[mt][nt][1]),
                          "+f"(acc[mt][nt][2]), "+f"(acc[mt][nt][3])
                        : "r"(ah[0]), "r"(ah[1]), "r"(ah[2]), "r"(ah[3]),
                          "r"(b0), "r"(b1));
                    asm volatile(
                        "mma.sync.aligned.m16n8k16.row.col.f32.bf16.bf16.f32 "
                        "{%0,%1,%2,%3}, {%4,%5,%6,%7}, {%8,%9}, {%0,%1,%2,%3};"
                        : "+f"(acc[mt][nt][0]), "+f"(acc[mt][nt][1]),
                          "+f"(acc[mt][nt][2]), "+f"(acc[mt][nt][3])
                        : "r"(al[0]), "r"(al[1]), "r"(al[2]), "r"(al[3]),
                          "r"(b0), "r"(b1));
                    asm volatile(
                        "mma.sync.aligned.m16n8k16.row.col.f32.bf16.bf16.f32 "
                        "{%0,%1,%2,%3}, {%4,%5,%6,%7}, {%8,%9}, {%0,%1,%2,%3};"
                        : "+f"(acc[mt][nt][0]), "+f"(acc[mt][nt][1]),
                          "+f"(acc[mt][nt][2]), "+f"(acc[mt][nt][3])
                        : "r"(ah[0]), "r"(ah[1]), "r"(ah[2]), "r"(ah[3]),
                          "r"(c0), "r"(c1));
                }
            }
        }
        __syncthreads();
        if (++buf == 3) buf = 0;
    }

    // epilogue
    const int qr = lane >> 2, qc = (lane & 3) * 2;
#pragma unroll
    for (int mt = 0; mt < 4; mt++) {
        int mA = m0 + wm + mt * 16 + qr;
        int mB = mA + 8;
        int rA = (flags & 2) ? ((mA & (B_ - 1)) * T_ + (mA >> 7)) : mA;
        int rB = (flags & 2) ? ((mB & (B_ - 1)) * T_ + (mB >> 7)) : mB;
        float* C0 = C + (size_t)rA * ldc;
        float* C1 = C + (size_t)rB * ldc;
#pragma unroll
        for (int nt = 0; nt < 4; nt++) {
            int n = n0 + wn + nt * 8 + qc;
            if (n < N) {
                float bia0 = bias ? bias[n] : 0.f;
                float bia1 = bias ? bias[n + 1] : 0.f;
                float v0 = acc[mt][nt][0] + bia0;
                float v1 = acc[mt][nt][1] + bia1;
                float v2 = acc[mt][nt][2] + bia0;
                float v3 = acc[mt][nt][3] + bia1;
                if (flags & 1) {
                    v0 = tanhf(v0); v1 = tanhf(v1);
                    v2 = tanhf(v2); v3 = tanhf(v3);
                }
                C0[n] = v0; C0[n + 1] = v1;
                C1[n] = v2; C1[n + 1] = v3;
            }
        }
    }
}

// ---------------------------------------------------------------------------
// f32x2 GEMM (tiny "hidden" projection only)
// ---------------------------------------------------------------------------
__global__ __launch_bounds__(256) void gemm128(
    const float* __restrict__ A, int lda,
    const float* __restrict__ B, int ldb,
    const float* __restrict__ bias,
    float* __restrict__ C, int ldc,
    int N, int K, int flags)
{
    __shared__ __align__(16) float As[16][132];
    __shared__ __align__(16) float Bs[16][132];
    const int tid = threadIdx.x;
    const int m0 = blockIdx.y * 128;
    const int n0 = blockIdx.x * 128;
    const int tx = tid & 15, ty = tid >> 4;
    const int tm0 = ty * 8, tn0 = tx * 8;
    const int lr = tid >> 2;
    const int kq = (tid & 3) * 4;

    ull acc[8][4];
#pragma unroll
    for (int i = 0; i < 8; i++)
#pragma unroll
        for (int j = 0; j < 4; j++) acc[i][j] = 0ull;

    const float* Ap0 = A + (size_t)(m0 + lr) * lda + kq;
    const float* Ap1 = A + (size_t)(m0 + lr + 64) * lda + kq;
    const int nb0 = n0 + lr, nb1 = n0 + lr + 64;
    const float* Bp0 = B + (size_t)nb0 * ldb + kq;
    const float* Bp1 = B + (size_t)nb1 * ldb + kq;
    const bool v0 = nb0 < N, v1 = nb1 < N;
    const float4 z4 = make_float4(0.f, 0.f, 0.f, 0.f);

    float4 ra0 = *(const float4*)Ap0;
    float4 ra1 = *(const float4*)Ap1;
    float4 rb0 = v0 ? *(const float4*)Bp0 : z4;
    float4 rb1 = v1 ? *(const float4*)Bp1 : z4;

    for (int k0 = 0; k0 < K; k0 += 16) {
        __syncthreads();
        As[kq+0][lr] = ra0.x; As[kq+1][lr] = ra0.y;
        As[kq+2][lr] = ra0.z; As[kq+3][lr] = ra0.w;
        As[kq+0][lr+64] = ra1.x; As[kq+1][lr+64] = ra1.y;
        As[kq+2][lr+64] = ra1.z; As[kq+3][lr+64] = ra1.w;
        Bs[kq+0][lr] = rb0.x; Bs[kq+1][lr] = rb0.y;
        Bs[kq+2][lr] = rb0.z; Bs[kq+3][lr] = rb0.w;
        Bs[kq+0][lr+64] = rb1.x; Bs[kq+1][lr+64] = rb1.y;
        Bs[kq+2][lr+64] = rb1.z; Bs[kq+3][lr+64] = rb1.w;
        __syncthreads();
        if (k0 + 16 < K) {
            Ap0 += 16; Ap1 += 16; Bp0 += 16; Bp1 += 16;
            ra0 = *(const float4*)Ap0;
            ra1 = *(const float4*)Ap1;
            rb0 = v0 ? *(const float4*)Bp0 : z4;
            rb1 = v1 ? *(const float4*)Bp1 : z4;
        }
#pragma unroll
        for (int kk = 0; kk < 16; kk++) {
            float4 af0 = *(const float4*)&As[kk][tm0];
            float4 af1 = *(const float4*)&As[kk][tm0 + 4];
            ulonglong2 b01 = *(const ulonglong2*)&Bs[kk][tn0];
            ulonglong2 b23 = *(const ulonglong2*)&Bs[kk][tn0 + 4];
            const ull bp0 = b01.x, bp1 = b01.y, bp2 = b23.x, bp3 = b23.y;
            float av[8] = {af0.x, af0.y, af0.z, af0.w,
                           af1.x, af1.y, af1.z, af1.w};
#pragma unroll
            for (int i = 0; i < 8; i++) {
                ull ap = pk2(av[i], av[i]);
                fma2(acc[i][0], ap, bp0);
                fma2(acc[i][1], ap, bp1);
                fma2(acc[i][2], ap, bp2);
                fma2(acc[i][3], ap, bp3);
            }
        }
    }

#pragma unroll
    for (int i = 0; i < 8; i++) {
        int m = m0 + tm0 + i;
        float* Cp = C + (size_t)m * ldc;
#pragma unroll
        for (int j = 0; j < 4; j++) {
            float lo, hi; upk2(acc[i][j], lo, hi);
            int n = n0 + tn0 + 2 * j;
            if (n < N) {
                float v = lo + (bias ? bias[n] : 0.f);
                if (flags & 1) v = tanhf(v);
                Cp[n] = v;
            }
            if (n + 1 < N) {
                float v = hi + (bias ? bias[n + 1] : 0.f);
                if (flags & 1) v = tanhf(v);
                Cp[n + 1] = v;
            }
        }
    }
}

// ---------------------------------------------------------------------------
// Decoder GEMM 1 (fused gh + q, split-K)
// ---------------------------------------------------------------------------
__global__ __launch_bounds__(256) void dec_gemm_hq(
    const float* __restrict__ Whh, const float* __restrict__ attnW)
{
    __shared__ __align__(16) float As[16][132];
    __shared__ __align__(16) float Bs[16][36];
    const int tid = threadIdx.x;
    const int n0 = blockIdx.x * 32;
    const int k0base = blockIdx.y * 256;
    const int tx = tid & 7, ty = tid >> 3;
    const int tm0 = ty * 4, tn0 = tx * 4;
    const int alr = tid >> 1, akq = (tid & 1) * 8;
    const int bn = n0 + (tid >> 2), bkq = (tid & 3) * 4, bnl = tid >> 2;

    const float* Ap = g_h + (size_t)alr * D_ + k0base + akq;
    const float* Bp = (bn < 1536)
        ? (Whh + (size_t)bn * D_ + k0base + bkq)
        : (attnW + (size_t)(bn - 1536) * (D_ + 2*E_) + k0base + bkq);

    ull acc[4][2];
#pragma unroll
    for (int i = 0; i < 4; i++) { acc[i][0] = 0ull; acc[i][1] = 0ull; }

    float4 ra0 = *(const float4*)Ap;
    float4 ra1 = *(const float4*)(Ap + 4);
    float4 rb;
    if (tid < 128) rb = *(const float4*)Bp;

    for (int kc = 0; kc < 16; kc++) {
        __syncthreads();
        As[akq+0][alr] = ra0.x; As[akq+1][alr] = ra0.y;
        As[akq+2][alr] = ra0.z; As[akq+3][alr] = ra0.w;
        As[akq+4][alr] = ra1.x; As[akq+5][alr] = ra1.y;
        As[akq+6][alr] = ra1.z; As[akq+7][alr] = ra1.w;
        if (tid < 128) {
            Bs[bkq+0][bnl] = rb.x; Bs[bkq+1][bnl] = rb.y;
            Bs[bkq+2][bnl] = rb.z; Bs[bkq+3][bnl] = rb.w;
        }
        __syncthreads();
        if (kc < 15) {
            Ap += 16;
            ra0 = *(const float4*)Ap;
            ra1 = *(const float4*)(Ap + 4);
            if (tid < 128) { Bp += 16; rb = *(const float4*)Bp; }
        }
#pragma unroll
        for (int kk = 0; kk < 16; kk++) {
            float4 a = *(const float4*)&As[kk][tm0];
            ulonglong2 b = *(const ulonglong2*)&Bs[kk][tn0];
            float av[4] = {a.x, a.y, a.z, a.w};
#pragma unroll
            for (int i = 0; i < 4; i++) {
                ull ap = pk2(av[i], av[i]);
                fma2(acc[i][0], ap, b.x);
                fma2(acc[i][1], ap, b.y);
            }
        }
    }

    float* P = g_p1 + (size_t)blockIdx.y * (B_ * 2048);
#pragma unroll
    for (int i = 0; i < 4; i++) {
        float* Pp = P + (size_t)(tm0 + i) * 2048 + n0 + tn0;
#pragma unroll
        for (int j = 0; j < 2; j++) {
            float lo, hi; upk2(acc[i][j], lo, hi);
            Pp[2*j] = lo; Pp[2*j + 1] = hi;
        }
    }
}

// ---------------------------------------------------------------------------
// Decoder GEMM 2 (gi from weighted, split-K)
// ---------------------------------------------------------------------------
__global__ __launch_bounds__(256) void dec_gemm_gi(
    const float* __restrict__ Wih, int t_step)
{
    __shared__ __align__(16) float As[16][132];
    __shared__ __align__(16) float Bs[16][36];
    const int tid = threadIdx.x;
    const int n0 = blockIdx.x * 32;
    const int k0base = blockIdx.y * 256;
    const int tx = tid & 7, ty = tid >> 3;
    const int tm0 = ty * 4, tn0 = tx * 4;
    const int alr = tid >> 1, akq = (tid & 1) * 8;
    const int bn = n0 + (tid >> 2), bkq = (tid & 3) * 4, bnl = tid >> 2;

    const float* Ap = g_feat + ((size_t)t_step * B_ + alr) * FEAT_ + D_ + k0base + akq;
    const float* Bp = Wih + (size_t)bn * (EMB_ + 2*E_) + EMB_ + k0base + bkq;

    ull acc[4][2];
#pragma unroll
    for (int i = 0; i < 4; i++) { acc[i][0] = 0ull; acc[i][1] = 0ull; }

    float4 ra0 = *(const float4*)Ap;
    float4 ra1 = *(const float4*)(Ap + 4);
    float4 rb;
    if (tid < 128) rb = *(const float4*)Bp;

    for (int kc = 0; kc < 16; kc++) {
        __syncthreads();
        As[akq+0][alr] = ra0.x; As[akq+1][alr] = ra0.y;
        As[akq+2][alr] = ra0.z; As[akq+3][alr] = ra0.w;
        As[akq+4][alr] = ra1.x; As[akq+5][alr] = ra1.y;
        As[akq+6][alr] = ra1.z; As[akq+7][alr] = ra1.w;
        if (tid < 128) {
            Bs[bkq+0][bnl] = rb.x; Bs[bkq+1][bnl] = rb.y;
            Bs[bkq+2][bnl] = rb.z; Bs[bkq+3][bnl] = rb.w;
        }
        __syncthreads();
        if (kc < 15) {
            Ap += 16;
            ra0 = *(const float4*)Ap;
            ra1 = *(const float4*)(Ap + 4);
            if (tid < 128) { Bp += 16; rb = *(const float4*)Bp; }
        }
#pragma unroll
        for (int kk = 0; kk < 16; kk++) {
            float4 a = *(const float4*)&As[kk][tm0];
            ulonglong2 b = *(const ulonglong2*)&Bs[kk][tn0];
            float av[4] = {a.x, a.y, a.z, a.w};
#pragma unroll
            for (int i = 0; i < 4; i++) {
                ull ap = pk2(av[i], av[i]);
                fma2(acc[i][0], ap, b.x);
                fma2(acc[i][1], ap, b.y);
            }
        }
    }

    float* P = g_p2 + (size_t)blockIdx.y * (B_ * 1536);
#pragma unroll
    for (int i = 0; i < 4; i++) {
        float* Pp = P + (size_t)(tm0 + i) * 1536 + n0 + tn0;
#pragma unroll
        for (int j = 0; j < 2; j++) {
            float lo, hi; upk2(acc[i][j], lo, hi);
            Pp[2*j] = lo; Pp[2*j + 1] = hi;
        }
    }
}

// ---------------------------------------------------------------------------
// Whh transpose
// ---------------------------------------------------------------------------
__global__ void transp_k(const float* __restrict__ Wf, const float* __restrict__ Wb)
{
    const int k = blockIdx.x, dir = blockIdx.y, e = threadIdx.x;
    const float* W = dir ? Wb : Wf;
    g_WhhT[dir * (E_*E_) + k * E_ + e] = W[e * E_ + k];
}

// ---------------------------------------------------------------------------
// Encoder recurrence  (pre layout: row-major (S*B, 512) = [f | b])
// ---------------------------------------------------------------------------
__global__ __launch_bounds__(256) void enc_rnn(
    const float* __restrict__ bhh_f, const float* __restrict__ bhh_b)
{
    __shared__ __align__(16) float hsh[E_ * 4];
    const int t = threadIdx.x;
    const int dir = blockIdx.y;
    const int b0 = blockIdx.x * 4;
    const float* WT = g_WhhT + dir * (E_*E_);
    const float* pre = g_pre + dir * E_;
    const float bias = dir ? bhh_b[t] : bhh_f[t];

#pragma unroll
    for (int b = 0; b < 4; b++) hsh[t * 4 + b] = 0.f;
    __syncthreads();

    float hcur[4] = {0.f, 0.f, 0.f, 0.f};
    for (int step = 0; step < S_; step++) {
        const int s = dir ? (S_ - 1 - step) : step;
        ull a01a = 0ull, a23a = 0ull, a01b = 0ull, a23b = 0ull;
        const float* wp = WT + t;
#pragma unroll 4
        for (int k = 0; k < E_; k += 2) {
            float w0 = __ldg(wp + (size_t)k * E_);
            float w1 = __ldg(wp + (size_t)(k + 1) * E_);
            ull h01_0 = *(const ull*)&hsh[k * 4];
            ull h23_0 = *(const ull*)&hsh[k * 4 + 2];
            ull h01_1 = *(const ull*)&hsh[(k + 1) * 4];
            ull h23_1 = *(const ull*)&hsh[(k + 1) * 4 + 2];
            ull w0p = pk2(w0, w0), w1p = pk2(w1, w1);
            fma2(a01a, h01_0, w0p);
            fma2(a23a, h23_0, w0p);
            fma2(a01b, h01_1, w1p);
            fma2(a23b, h23_1, w1p);
        }
        float r0, r1, r2, r3, s0, s1, s2, s3;
        upk2(a01a, r0, r1); upk2(a23a, r2, r3);
        upk2(a01b, s0, s1); upk2(a23b, s2, s3);
        float dot[4] = {r0 + s0, r1 + s1, r2 + s2, r3 + s3};
        __syncthreads();
#pragma unroll
        for (int b = 0; b < 4; b++) {
            int row = s * B_ + b0 + b;
            float h = tanhf(pre[(size_t)row * 512 + t] + dot[b] + bias);
            hcur[b] = h;
            hsh[t * 4 + b] = h;
            g_enc_out[(size_t)row * (2*E_) + dir * E_ + t] = h;
        }
        __syncthreads();
    }
#pragma unroll
    for (int b = 0; b < 4; b++)
        g_hcat[(size_t)(b0 + b) * (2*E_) + dir * E_ + t] = hcur[b];
}

// ---------------------------------------------------------------------------
// Embedding gather -> feat[..., 1024:1280]
// ---------------------------------------------------------------------------
__global__ void embed_k(const int* __restrict__ trg, const float* __restrict__ table)
{
    const int m = blockIdx.x;
    const int e = threadIdx.x;
    const int t = m >> 7, b = m & (B_ - 1);
    const int tok = trg[b * T_ + t];
    g_feat[(size_t)m * FEAT_ + (D_ + 2*E_) + e] = table[(size_t)tok * EMB_ + e];
}

// ---------------------------------------------------------------------------
// Fused attention: q from split-K partials -> scores -> softmax -> weighted
// ---------------------------------------------------------------------------
__global__ __launch_bounds__(512) void attn_fused_k(
    const float* __restrict__ attn_v, int t_step)
{
    __shared__ __align__(16) float qs[D_];
    __shared__ __align__(16) float vs[D_];
    __shared__ float sc[S_];
    const int b = blockIdx.x;
    const int tid = threadIdx.x;
    const int w = tid >> 5, lane = tid & 31;

    qs[tid] = g_p1[(size_t)b * 2048 + 1536 + tid]
            + g_p1[(size_t)(B_ + b) * 2048 + 1536 + tid];
    vs[tid] = attn_v[tid];
    __syncthreads();

    const float4* qp = (const float4*)qs;
    const float4* vp = (const float4*)vs;
#pragma unroll
    for (int i = 0; i < 8; i++) {
        int s = w + i * 16;
        const float4* ep = (const float4*)(g_enc_part + (size_t)(s * B_ + b) * D_);
        float acc = 0.f;
#pragma unroll
        for (int j = 0; j < 4; j++) {
            int idx = lane + 32 * j;
            float4 e = ep[idx]; float4 q = qp[idx]; float4 v = vp[idx];
            acc += tanhf(e.x + q.x) * v.x + tanhf(e.y + q.y) * v.y
                 + tanhf(e.z + q.z) * v.z + tanhf(e.w + q.w) * v.w;
        }
#pragma unroll
        for (int o = 16; o; o >>= 1) acc += __shfl_xor_sync(0xffffffffu, acc, o);
        if (lane == 0) sc[s] = acc;
    }
    __syncthreads();

    if (tid < 32) {
        float v[4]; float m = -1e30f;
#pragma unroll
        for (int i = 0; i < 4; i++) { v[i] = sc[tid + 32 * i]; m = fmaxf(m, v[i]); }
#pragma unroll
        for (int o = 16; o; o >>= 1) m = fmaxf(m, __shfl_xor_sync(0xffffffffu, m, o));
        float s = 0.f;
#pragma unroll
        for (int i = 0; i < 4; i++) { v[i] = expf(v[i] - m); s += v[i]; }
#pragma unroll
        for (int o = 16; o; o >>= 1) s += __shfl_xor_sync(0xffffffffu, s, o);
        float inv = 1.f / s;
#pragma unroll
        for (int i = 0; i < 4; i++) sc[tid + 32 * i] = v[i] * inv;
    }
    __syncthreads();

    const int e = tid;
    const float* eo = g_enc_out + (size_t)b * (2*E_) + e;
    float acc = 0.f;
#pragma unroll 4
    for (int s = 0; s < S_; s++)
        acc += sc[s] * eo[(size_t)s * B_ * (2*E_)];
    g_feat[((size_t)t_step * B_ + b) * FEAT_ + D_ + e] = acc;
}

// ---------------------------------------------------------------------------
// GRU pointwise update (combines split-K partials + biases inline)
// ---------------------------------------------------------------------------
__global__ __launch_bounds__(512) void gru_k(int t_step,
    const float* __restrict__ bhh, const float* __restrict__ bih)
{
    const int b = blockIdx.x, d = threadIdx.x;
    const size_t m = (size_t)t_step * B_ + b;
    const float* p1a = g_p1 + (size_t)b * 2048;
    const float* p1b = g_p1 + (size_t)(B_ + b) * 2048;
    const float* p2a = g_p2 + (size_t)b * 1536;
    const float* p2b = g_p2 + (size_t)(B_ + b) * 1536;
    const float* ge = g_gi_emb + m * (3*D_);

    float gh_r = p1a[d] + p1b[d] + bhh[d];
    float gh_z = p1a[d + D_] + p1b[d + D_] + bhh[d + D_];
    float gh_n = p1a[d + 2*D_] + p1b[d + 2*D_] + bhh[d + 2*D_];
    float gi_r = p2a[d] + p2b[d] + bih[d];
    float gi_z = p2a[d + D_] + p2b[d + D_] + bih[d + D_];
    float gi_n = p2a[d + 2*D_] + p2b[d + 2*D_] + bih[d + 2*D_];

    float xr = gi_r + ge[d] + gh_r;
    float xz = gi_z + ge[d + D_] + gh_z;
    float gin = gi_n + ge[d + 2*D_];
    float r = 1.f / (1.f + expf(-xr));
    float z = 1.f / (1.f + expf(-xz));
    float n = tanhf(gin + r * gh_n);
    float hold = g_h[(size_t)b * D_ + d];
    float hnew = (1.f - z) * n + z * hold;
    g_h[(size_t)b * D_ + d] = hnew;
    g_feat[m * FEAT_ + d] = hnew;
}

// ---------------------------------------------------------------------------
// Row softmax over V=10000 for a 4-step chunk: row = bIdx.y*T + t0 + bIdx.x
// ---------------------------------------------------------------------------
__global__ __launch_bounds__(512) void softmax_chunk_k(float* __restrict__ out,
                                                       int t0)
{
    const int row = blockIdx.y * T_ + t0 + blockIdx.x;
    float* p = out + (size_t)row * V_;
    const int tid = threadIdx.x, lane = tid & 31, w = tid >> 5;
    __shared__ float red[16];
    __shared__ float bc;
    float m = -1e30f;
    for (int i = tid; i < V_; i += 512) m = fmaxf(m, p[i]);
#pragma unroll
    for (int o = 16; o; o >>= 1) m = fmaxf(m, __shfl_xor_sync(0xffffffffu, m, o));
    if (lane == 0) red[w] = m;
    __syncthreads();
    if (tid == 0) {
        float mm = red[0];
        for (int i = 1; i < 16; i++) mm = fmaxf(mm, red[i]);
        bc = mm;
    }
    __syncthreads();
    m = bc;
    float s = 0.f;
    for (int i = tid; i < V_; i += 512) { float e = expf(p[i] - m); p[i] = e; s += e; }
#pragma unroll
    for (int o = 16; o; o >>= 1) s += __shfl_xor_sync(0xffffffffu, s, o);
    if (lane == 0) red[w] = s;
    __syncthreads();
    if (tid == 0) {
        float ss = 0.f;
        for (int i = 0; i < 16; i++) ss += red[i];
        bc = 1.f / ss;
    }
    __syncthreads();
    float inv = bc;
    for (int i = tid; i < V_; i += 512) p[i] *= inv;
}

// ---------------------------------------------------------------------------
// Host orchestration
// ---------------------------------------------------------------------------
extern "C" void kernel_launch(void* const* d_in, const int* in_sizes, int n_in,
                              void* d_out, int out_size)
{
    const float* src       = (const float*)d_in[0];
    const int*   trg       = (const int*)  d_in[1];
    const float* Wih_f     = (const float*)d_in[2];
    const float* Whh_f     = (const float*)d_in[3];
    const float* bih_f     = (const float*)d_in[4];
    const float* bhh_f     = (const float*)d_in[5];
    const float* Wih_b     = (const float*)d_in[6];
    const float* Whh_b     = (const float*)d_in[7];
    const float* bih_b     = (const float*)d_in[8];
    const float* bhh_b     = (const float*)d_in[9];
    const float* fcW       = (const float*)d_in[10];
    const float* fcb       = (const float*)d_in[11];
    const float* attn_W    = (const float*)d_in[12];
    const float* attn_b    = (const float*)d_in[13];
    const float* attn_v    = (const float*)d_in[14];
    const float* emb_table = (const float*)d_in[15];
    const float* gru_Wih   = (const float*)d_in[16];
    const float* gru_Whh   = (const float*)d_in[17];
    const float* gru_bih   = (const float*)d_in[18];
    const float* gru_bhh   = (const float*)d_in[19];
    const float* out_W     = (const float*)d_in[20];
    const float* out_b     = (const float*)d_in[21];
    float* out = (float*)d_out;

    // one-time stream/event setup (no device memory allocation)
    // s1 = LOW priority: its fat logits chunks only soak SM slots the
    // high-priority (default) decoder chain leaves idle.
    static cudaStream_t s1 = nullptr;
    static cudaEvent_t evc[8], evj;
    if (!s1) {
        int pLeast, pGreatest;
        cudaDeviceGetStreamPriorityRange(&pLeast, &pGreatest);
        cudaStreamCreateWithPriority(&s1, cudaStreamNonBlocking, pLeast);
        for (int i = 0; i < 8; i++)
            cudaEventCreateWithFlags(&evc[i], cudaEventDisableTiming);
        cudaEventCreateWithFlags(&evj, cudaEventDisableTiming);
    }

    void *vp;
    cudaGetSymbolAddress(&vp, g_pre);      float* pre_p      = (float*)vp;
    cudaGetSymbolAddress(&vp, g_enc_out);  float* enc_out_p  = (float*)vp;
    cudaGetSymbolAddress(&vp, g_enc_part); float* enc_part_p = (float*)vp;
    cudaGetSymbolAddress(&vp, g_hcat);     float* hcat_p     = (float*)vp;
    cudaGetSymbolAddress(&vp, g_h);        float* h_p        = (float*)vp;
    cudaGetSymbolAddress(&vp, g_gi_emb);   float* gi_emb_p   = (float*)vp;
    cudaGetSymbolAddress(&vp, g_feat);     float* feat_p     = (float*)vp;
    cudaGetSymbolAddress(&vp, g_bpre);     float* bpre_p     = (float*)vp;
    cudaGetSymbolAddress(&vp, g_A2);       __nv_bfloat16* A2_p    = (__nv_bfloat16*)vp;
    cudaGetSymbolAddress(&vp, g_B2);       __nv_bfloat16* B2_p    = (__nv_bfloat16*)vp;
    cudaGetSymbolAddress(&vp, gA2_src);    __nv_bfloat16* A2src_p = (__nv_bfloat16*)vp;
    cudaGetSymbolAddress(&vp, gB2_pre);    __nv_bfloat16* B2pre_p = (__nv_bfloat16*)vp;
    cudaGetSymbolAddress(&vp, gA2_enc);    __nv_bfloat16* A2enc_p = (__nv_bfloat16*)vp;
    cudaGetSymbolAddress(&vp, gB2_attn);   __nv_bfloat16* B2att_p = (__nv_bfloat16*)vp;
    cudaGetSymbolAddress(&vp, gA2_emb);    __nv_bfloat16* A2emb_p = (__nv_bfloat16*)vp;
    cudaGetSymbolAddress(&vp, gB2_wih);    __nv_bfloat16* B2wih_p = (__nv_bfloat16*)vp;

    cudaFuncSetAttribute(gemm_hmma,
                         cudaFuncAttributeMaxDynamicSharedMemorySize, HMMA_SMEM);

    // out_W split on s1 — overlaps the whole encoder phase
    split2_k<<<dim3(5, VPAD_), 256, 0, s1>>>(out_W, FEAT_, FEAT_, V_, B2_p);

    // --- encoder (main stream) ---
    cat_bias_k<<<2, 256>>>(bih_f, bih_b);
    splitB2_pre_k<<<dim3(1, 512), 256>>>(Wih_f, Wih_b);
    split2_k<<<dim3(1, 16384), 256>>>(src, C_, 256, 16384, A2src_p);
    gemm_hmma<<<dim3(4, 128), 256, HMMA_SMEM>>>(A2src_p, B2pre_p, bpre_p,
                                                pre_p, 512, 512, 8, 0, 0);
    transp_k<<<dim3(256, 2), 256>>>(Whh_f, Whh_b);
    enc_rnn<<<dim3(32, 2), 256>>>(bhh_f, bhh_b);
    gemm128<<<dim3(4, 1), 256>>>(hcat_p, 2*E_, fcW, 2*E_, fcb,
                                 h_p, D_, D_, 2*E_, 1);
    split2_k<<<dim3(2, 16384), 256>>>(enc_out_p, 2*E_, 512, 16384, A2enc_p);
    split2_k<<<dim3(2, 512), 256>>>(attn_W + D_, D_ + 2*E_, 512, 512, B2att_p);
    gemm_hmma<<<dim3(4, 128), 256, HMMA_SMEM>>>(A2enc_p, B2att_p, attn_b,
                                                enc_part_p, 512, 512, 16, 0, 0);
    embed_k<<<T_ * B_, EMB_>>>(trg, emb_table);
    split2_k<<<dim3(1, 4096), 256>>>(feat_p + (D_ + 2*E_), FEAT_, 256, 4096,
                                     A2emb_p);
    split2_k<<<dim3(1, 1536), 256>>>(gru_Wih, EMB_ + 2*E_, 256, 1536, B2wih_p);
    gemm_hmma<<<dim3(12, 32), 256, HMMA_SMEM>>>(A2emb_p, B2wih_p,
                                                (const float*)nullptr,
                                                gi_emb_p, 3*D_, 3*D_, 8, 0, 0);

    // --- decoder; every 4 steps a 512-row logits chunk + softmax on s1 ---
    for (int t = 0; t < T_; t++) {
        dec_gemm_hq<<<dim3(64, 2), 256>>>(gru_Whh, attn_W);
        attn_fused_k<<<B_, 512>>>(attn_v, t);
        dec_gemm_gi<<<dim3(48, 2), 256>>>(gru_Wih, t);
        gru_k<<<B_, 512>>>(t, gru_bhh, gru_bih);
        if ((t & 3) == 3) {
            int c = t >> 2;
            cudaEventRecord(evc[c], 0);
            cudaStreamWaitEvent(s1, evc[c], 0);
            split2_k<<<dim3(5, 512), 256, 0, s1>>>(
                feat_p + (size_t)c * 512 * FEAT_, FEAT_, FEAT_, 512,
                A2_p + (size_t)c * 512 * 2560);
            gemm_hmma<<<dim3(VPAD_ / 128, 4), 256, HMMA_SMEM, s1>>>(
                A2_p, B2_p, out_b, out, V_, V_, 40, 2, c * 512);
            softmax_chunk_k<<<dim3(4, 128), 512, 0, s1>>>(out, c * 4);
        }
    }
    cudaEventRecord(evj, s1);
    cudaStreamWaitEvent(0, evj, 0);
}

// round 14
// speedup vs baseline: 1.0666x; 1.0666x over previous
#include <cuda_runtime.h>
#include <cuda_bf16.h>
#include <cstdint>

// ---------------------------------------------------------------------------
// Problem constants
// ---------------------------------------------------------------------------
#define S_   128
#define B_   128
#define C_   256
#define E_   256
#define D_   512
#define EMB_ 256
#define V_   10000
#define T_   32
#define FEAT_ (D_ + 2*E_ + EMB_)   // 1280
#define VPAD_ 10240

typedef unsigned long long ull;

// ---------------------------------------------------------------------------
// Scratch (__device__ globals; allocation-free)
// ---------------------------------------------------------------------------
__device__ float g_pre[S_ * B_ * 512];               // (S*B, 512) = [f|b]
__device__ float g_WhhT[2 * E_ * E_];
__device__ float g_enc_out[S_ * B_ * 2 * E_];
__device__ float g_enc_part[S_ * B_ * D_];
__device__ float g_hcat[B_ * 2 * E_];
__device__ float g_h[B_ * D_];
__device__ float g_gi_emb[T_ * B_ * 3 * D_];
__device__ float g_feat[T_ * B_ * FEAT_];
__device__ float g_p1[2 * B_ * 2048];                // split-K partials (gh|q)
__device__ float g_p2[2 * B_ * 1536];                // split-K partials (gi)
__device__ float g_bpre[512];

// factored split-bf16 operands: per row, K/32 blocks of [h(32)|l(32)]
__device__ __align__(16) __nv_bfloat16 g_A2[(size_t)(T_ * B_) * 2560];
__device__ __align__(16) __nv_bfloat16 g_B2[(size_t)VPAD_ * 2560];
__device__ __align__(16) __nv_bfloat16 gA2_src[(size_t)16384 * 512];
__device__ __align__(16) __nv_bfloat16 gB2_pre[512 * 512];
__device__ __align__(16) __nv_bfloat16 gA2_enc[(size_t)16384 * 1024];
__device__ __align__(16) __nv_bfloat16 gB2_attn[512 * 1024];
__device__ __align__(16) __nv_bfloat16 gA2_emb[4096 * 512];
__device__ __align__(16) __nv_bfloat16 gB2_wih[1536 * 512];

// ---------------------------------------------------------------------------
// helpers
// ---------------------------------------------------------------------------
__device__ __forceinline__ ull pk2(float lo, float hi) {
    ull r;
    asm("mov.b64 %0, {%1, %2};" : "=l"(r) : "f"(lo), "f"(hi));
    return r;
}
__device__ __forceinline__ void upk2(ull v, float& lo, float& hi) {
    asm("mov.b64 {%0, %1}, %2;" : "=f"(lo), "=f"(hi) : "l"(v));
}
__device__ __forceinline__ void fma2(ull& d, ull a, ull b) {
    asm("fma.rn.f32x2 %0, %1, %2, %0;" : "+l"(d) : "l"(a), "l"(b));
}
__device__ __forceinline__ uint32_t smem_u32(const void* p) {
    uint32_t a;
    asm("{ .reg .u64 t; cvta.to.shared.u64 t, %1; cvt.u32.u64 %0, t; }"
        : "=r"(a) : "l"(p));
    return a;
}
// write one fp32 value into the factored A2 layout at (row m, k)
__device__ __forceinline__ void a2_write(__nv_bfloat16* A2, size_t m, int k,
                                         float x) {
    __nv_bfloat16 h = __float2bfloat16(x);
    __nv_bfloat16 l = __float2bfloat16(x - __bfloat162float(h));
    size_t base = m * 2560 + (size_t)(k >> 5) * 64 + (k & 31);
    A2[base] = h;
    A2[base + 32] = l;
}

// ---------------------------------------------------------------------------
// split fp32 -> factored bf16 [h(32)|l(32)] per 32-element K block.
// ---------------------------------------------------------------------------
__global__ __launch_bounds__(256) void split2_k(
    const float* __restrict__ src, int lda, int Kf, int realRows,
    __nv_bfloat16* __restrict__ dst)
{
    const int k = blockIdx.x * 256 + threadIdx.x;
    const int r = blockIdx.y;
    float x = (r < realRows) ? src[(size_t)r * lda + k] : 0.f;
    __nv_bfloat16 h = __float2bfloat16(x);
    __nv_bfloat16 l = __float2bfloat16(x - __bfloat162float(h));
    size_t base = (size_t)r * 2 * Kf + (size_t)(k >> 5) * 64 + (k & 31);
    dst[base] = h;
    dst[base + 32] = l;
}

__global__ __launch_bounds__(256) void splitB2_pre_k(
    const float* __restrict__ Wf, const float* __restrict__ Wb)
{
    const int k = threadIdx.x;
    const int r = blockIdx.y;
    const float* W = (r < 256) ? Wf : Wb;
    float x = W[(size_t)(r & 255) * 256 + k];
    __nv_bfloat16 h = __float2bfloat16(x);
    __nv_bfloat16 l = __float2bfloat16(x - __bfloat162float(h));
    size_t base = (size_t)r * 512 + (size_t)(k >> 5) * 64 + (k & 31);
    gB2_pre[base] = h;
    gB2_pre[base + 32] = l;
}

__global__ void cat_bias_k(const float* __restrict__ a, const float* __restrict__ b)
{
    int i = blockIdx.x * 256 + threadIdx.x;
    g_bpre[i] = (i < 256) ? a[i] : b[i - 256];
}

// ---------------------------------------------------------------------------
// Factored split-bf16 HMMA GEMM (R9-proven config, interleaved LDSM/MMA)
// flags: bit0 = tanh, bit1 = (b,t) scatter for logits.
// ---------------------------------------------------------------------------
#define L3 72                          // bf16 per smem row (144 B)
#define HSTG_A (128 * L3 * 2)          // 18432 B
#define HSTG   (2 * HSTG_A)            // 36864 B (A + B)
#define HMMA_SMEM (3 * HSTG)           // 110592 B

__global__ __launch_bounds__(256, 2) void gemm_hmma(
    const __nv_bfloat16* __restrict__ A2, const __nv_bfloat16* __restrict__ B2,
    const float* __restrict__ bias, float* __restrict__ C,
    int ldc, int N, int NCH, int flags, int m_base)
{
    extern __shared__ __align__(16) char sm[];
    const uint32_t sbase = smem_u32(sm);
    const int tid = threadIdx.x, wid = tid >> 5, lane = tid & 31;
    const int m0 = m_base + blockIdx.y * 128, n0 = blockIdx.x * 128;
    const size_t ldk = (size_t)NCH * 64;

    const int lrow = tid >> 3;
    const int lcg  = tid & 7;
    const __nv_bfloat16* gA = A2 + (size_t)m0 * ldk;
    const __nv_bfloat16* gB = B2 + (size_t)n0 * ldk;

    float acc[4][4][4];
#pragma unroll
    for (int a = 0; a < 4; a++)
#pragma unroll
        for (int b = 0; b < 4; b++)
#pragma unroll
            for (int c = 0; c < 4; c++) acc[a][b][c] = 0.f;

    const int wr = wid >> 2, wc = wid & 3;
    const int wm = wr * 64, wn = wc * 32;

    auto issue_stage = [&](int c, int buf) {
        uint32_t sa = sbase + buf * HSTG;
        uint32_t sb = sa + HSTG_A;
        size_t kof = (size_t)c * 64 + lcg * 8;
#pragma unroll
        for (int i = 0; i < 4; i++) {
            int row = lrow + i * 32;
            uint32_t da = sa + (uint32_t)(row * L3 + lcg * 8) * 2;
            const void* pa = gA + (size_t)row * ldk + kof;
            asm volatile("cp.async.cg.shared.global [%0], [%1], 16;"
                         :: "r"(da), "l"(pa));
            uint32_t db = sb + (uint32_t)(row * L3 + lcg * 8) * 2;
            const void* pb = gB + (size_t)row * ldk + kof;
            asm volatile("cp.async.cg.shared.global [%0], [%1], 16;"
                         :: "r"(db), "l"(pb));
        }
        asm volatile("cp.async.commit_group;" ::: "memory");
    };

    issue_stage(0, 0);
    issue_stage(1, 1);

    int buf = 0;
    for (int c = 0; c < NCH; c++) {
        if (c + 2 < NCH) {
            int nb = buf + 2; if (nb >= 3) nb -= 3;
            issue_stage(c + 2, nb);
            asm volatile("cp.async.wait_group 2;" ::: "memory");
        } else if (c + 1 < NCH) {
            asm volatile("cp.async.wait_group 1;" ::: "memory");
        } else {
            asm volatile("cp.async.wait_group 0;" ::: "memory");
        }
        __syncthreads();

        const uint32_t sa  = sbase + buf * HSTG;
        const uint32_t sbm = sa + HSTG_A;

#pragma unroll
        for (int ks = 0; ks < 2; ks++) {
            const int acol = ks * 16 + ((lane >> 4) << 3);
            const int bcol = ks * 16 + ((lane & 8) ? 8 : 0);
            uint32_t bh[2][4], bl[2][4];
#pragma unroll
            for (int j = 0; j < 2; j++) {
                int row = wn + j * 16 + (lane & 7) + ((lane & 16) ? 8 : 0);
                uint32_t ad = sbm + (uint32_t)(row * L3 + bcol) * 2;
                asm volatile(
                    "ldmatrix.sync.aligned.m8n8.x4.shared.b16 {%0,%1,%2,%3}, [%4];"
                    : "=r"(bh[j][0]), "=r"(bh[j][1]),
                      "=r"(bh[j][2]), "=r"(bh[j][3])
                    : "r"(ad));
                asm volatile(
                    "ldmatrix.sync.aligned.m8n8.x4.shared.b16 {%0,%1,%2,%3}, [%4];"
                    : "=r"(bl[j][0]), "=r"(bl[j][1]),
                      "=r"(bl[j][2]), "=r"(bl[j][3])
                    : "r"(ad + 64));
            }
#pragma unroll
            for (int mt = 0; mt < 4; mt++) {
                int row = wm + mt * 16 + (lane & 15);
                uint32_t ah[4], al[4];
                uint32_t aad = sa + (uint32_t)(row * L3 + acol) * 2;
                asm volatile(
                    "ldmatrix.sync.aligned.m8n8.x4.shared.b16 {%0,%1,%2,%3}, [%4];"
                    : "=r"(ah[0]), "=r"(ah[1]), "=r"(ah[2]), "=r"(ah[3])
                    : "r"(aad));
                asm volatile(
                    "ldmatrix.sync.aligned.m8n8.x4.shared.b16 {%0,%1,%2,%3}, [%4];"
                    : "=r"(al[0]), "=r"(al[1]), "=r"(al[2]), "=r"(al[3])
                    : "r"(aad + 64));
#pragma unroll
                for (int nt = 0; nt < 4; nt++) {
                    uint32_t b0 = bh[nt >> 1][(nt & 1) * 2 + 0];
                    uint32_t b1 = bh[nt >> 1][(nt & 1) * 2 + 1];
                    uint32_t c0 = bl[nt >> 1][(nt & 1) * 2 + 0];
                    uint32_t c1 = bl[nt >> 1][(nt & 1) * 2 + 1];
                    asm volatile(
                        "mma.sync.aligned.m16n8k16.row.col.f32.bf16.bf16.f32 "
                        "{%0,%1,%2,%3}, {%4,%5,%6,%7}, {%8,%9}, {%0,%1,%2,%3};"
                        : "+f"(acc[mt][nt][0]), "+f"(acc[mt][nt][1]),
                          "+f"(acc[mt][nt][2]), "+f"(acc[mt][nt][3])
                        : "r"(ah[0]), "r"(ah[1]), "r"(ah[2]), "r"(ah[3]),
                          "r"(b0), "r"(b1));
                    asm volatile(
                        "mma.sync.aligned.m16n8k16.row.col.f32.bf16.bf16.f32 "
                        "{%0,%1,%2,%3}, {%4,%5,%6,%7}, {%8,%9}, {%0,%1,%2,%3};"
                        : "+f"(acc[mt][nt][0]), "+f"(acc[mt][nt][1]),
                          "+f"(acc[mt][nt][2]), "+f"(acc[mt][nt][3])
                        : "r"(al[0]), "r"(al[1]), "r"(al[2]), "r"(al[3]),
                          "r"(b0), "r"(b1));
                    asm volatile(
                        "mma.sync.aligned.m16n8k16.row.col.f32.bf16.bf16.f32 "
                        "{%0,%1,%2,%3}, {%4,%5,%6,%7}, {%8,%9}, {%0,%1,%2,%3};"
                        : "+f"(acc[mt][nt][0]), "+f"(acc[mt][nt][1]),
                          "+f"(acc[mt][nt][2]), "+f"(acc[mt][nt][3])
                        : "r"(ah[0]), "r"(ah[1]), "r"(ah[2]), "r"(ah[3]),
                          "r"(c0), "r"(c1));
                }
            }
        }
        __syncthreads();
        if (++buf == 3) buf = 0;
    }

    // epilogue
    const int qr = lane >> 2, qc = (lane & 3) * 2;
#pragma unroll
    for (int mt = 0; mt < 4; mt++) {
        int mA = m0 + wm + mt * 16 + qr;
        int mB = mA + 8;
        int rA = (flags & 2) ? ((mA & (B_ - 1)) * T_ + (mA >> 7)) : mA;
        int rB = (flags & 2) ? ((mB & (B_ - 1)) * T_ + (mB >> 7)) : mB;
        float* C0 = C + (size_t)rA * ldc;
        float* C1 = C + (size_t)rB * ldc;
#pragma unroll
        for (int nt = 0; nt < 4; nt++) {
            int n = n0 + wn + nt * 8 + qc;
            if (n < N) {
                float bia0 = bias ? bias[n] : 0.f;
                float bia1 = bias ? bias[n + 1] : 0.f;
                float v0 = acc[mt][nt][0] + bia0;
                float v1 = acc[mt][nt][1] + bia1;
                float v2 = acc[mt][nt][2] + bia0;
                float v3 = acc[mt][nt][3] + bia1;
                if (flags & 1) {
                    v0 = tanhf(v0); v1 = tanhf(v1);
                    v2 = tanhf(v2); v3 = tanhf(v3);
                }
                C0[n] = v0; C0[n + 1] = v1;
                C1[n] = v2; C1[n + 1] = v3;
            }
        }
    }
}

// ---------------------------------------------------------------------------
// f32x2 GEMM (tiny "hidden" projection only)
// ---------------------------------------------------------------------------
__global__ __launch_bounds__(256) void gemm128(
    const float* __restrict__ A, int lda,
    const float* __restrict__ B, int ldb,
    const float* __restrict__ bias,
    float* __restrict__ C, int ldc,
    int N, int K, int flags)
{
    __shared__ __align__(16) float As[16][132];
    __shared__ __align__(16) float Bs[16][132];
    const int tid = threadIdx.x;
    const int m0 = blockIdx.y * 128;
    const int n0 = blockIdx.x * 128;
    const int tx = tid & 15, ty = tid >> 4;
    const int tm0 = ty * 8, tn0 = tx * 8;
    const int lr = tid >> 2;
    const int kq = (tid & 3) * 4;

    ull acc[8][4];
#pragma unroll
    for (int i = 0; i < 8; i++)
#pragma unroll
        for (int j = 0; j < 4; j++) acc[i][j] = 0ull;

    const float* Ap0 = A + (size_t)(m0 + lr) * lda + kq;
    const float* Ap1 = A + (size_t)(m0 + lr + 64) * lda + kq;
    const int nb0 = n0 + lr, nb1 = n0 + lr + 64;
    const float* Bp0 = B + (size_t)nb0 * ldb + kq;
    const float* Bp1 = B + (size_t)nb1 * ldb + kq;
    const bool v0 = nb0 < N, v1 = nb1 < N;
    const float4 z4 = make_float4(0.f, 0.f, 0.f, 0.f);

    float4 ra0 = *(const float4*)Ap0;
    float4 ra1 = *(const float4*)Ap1;
    float4 rb0 = v0 ? *(const float4*)Bp0 : z4;
    float4 rb1 = v1 ? *(const float4*)Bp1 : z4;

    for (int k0 = 0; k0 < K; k0 += 16) {
        __syncthreads();
        As[kq+0][lr] = ra0.x; As[kq+1][lr] = ra0.y;
        As[kq+2][lr] = ra0.z; As[kq+3][lr] = ra0.w;
        As[kq+0][lr+64] = ra1.x; As[kq+1][lr+64] = ra1.y;
        As[kq+2][lr+64] = ra1.z; As[kq+3][lr+64] = ra1.w;
        Bs[kq+0][lr] = rb0.x; Bs[kq+1][lr] = rb0.y;
        Bs[kq+2][lr] = rb0.z; Bs[kq+3][lr] = rb0.w;
        Bs[kq+0][lr+64] = rb1.x; Bs[kq+1][lr+64] = rb1.y;
        Bs[kq+2][lr+64] = rb1.z; Bs[kq+3][lr+64] = rb1.w;
        __syncthreads();
        if (k0 + 16 < K) {
            Ap0 += 16; Ap1 += 16; Bp0 += 16; Bp1 += 16;
            ra0 = *(const float4*)Ap0;
            ra1 = *(const float4*)Ap1;
            rb0 = v0 ? *(const float4*)Bp0 : z4;
            rb1 = v1 ? *(const float4*)Bp1 : z4;
        }
#pragma unroll
        for (int kk = 0; kk < 16; kk++) {
            float4 af0 = *(const float4*)&As[kk][tm0];
            float4 af1 = *(const float4*)&As[kk][tm0 + 4];
            ulonglong2 b01 = *(const ulonglong2*)&Bs[kk][tn0];
            ulonglong2 b23 = *(const ulonglong2*)&Bs[kk][tn0 + 4];
            const ull bp0 = b01.x, bp1 = b01.y, bp2 = b23.x, bp3 = b23.y;
            float av[8] = {af0.x, af0.y, af0.z, af0.w,
                           af1.x, af1.y, af1.z, af1.w};
#pragma unroll
            for (int i = 0; i < 8; i++) {
                ull ap = pk2(av[i], av[i]);
                fma2(acc[i][0], ap, bp0);
                fma2(acc[i][1], ap, bp1);
                fma2(acc[i][2], ap, bp2);
                fma2(acc[i][3], ap, bp3);
            }
        }
    }

#pragma unroll
    for (int i = 0; i < 8; i++) {
        int m = m0 + tm0 + i;
        float* Cp = C + (size_t)m * ldc;
#pragma unroll
        for (int j = 0; j < 4; j++) {
            float lo, hi; upk2(acc[i][j], lo, hi);
            int n = n0 + tn0 + 2 * j;
            if (n < N) {
                float v = lo + (bias ? bias[n] : 0.f);
                if (flags & 1) v = tanhf(v);
                Cp[n] = v;
            }
            if (n + 1 < N) {
                float v = hi + (bias ? bias[n + 1] : 0.f);
                if (flags & 1) v = tanhf(v);
                Cp[n + 1] = v;
            }
        }
    }
}

// ---------------------------------------------------------------------------
// Decoder GEMM 1 (fused gh + q, split-K)
// ---------------------------------------------------------------------------
__global__ __launch_bounds__(256) void dec_gemm_hq(
    const float* __restrict__ Whh, const float* __restrict__ attnW)
{
    __shared__ __align__(16) float As[16][132];
    __shared__ __align__(16) float Bs[16][36];
    const int tid = threadIdx.x;
    const int n0 = blockIdx.x * 32;
    const int k0base = blockIdx.y * 256;
    const int tx = tid & 7, ty = tid >> 3;
    const int tm0 = ty * 4, tn0 = tx * 4;
    const int alr = tid >> 1, akq = (tid & 1) * 8;
    const int bn = n0 + (tid >> 2), bkq = (tid & 3) * 4, bnl = tid >> 2;

    const float* Ap = g_h + (size_t)alr * D_ + k0base + akq;
    const float* Bp = (bn < 1536)
        ? (Whh + (size_t)bn * D_ + k0base + bkq)
        : (attnW + (size_t)(bn - 1536) * (D_ + 2*E_) + k0base + bkq);

    ull acc[4][2];
#pragma unroll
    for (int i = 0; i < 4; i++) { acc[i][0] = 0ull; acc[i][1] = 0ull; }

    float4 ra0 = *(const float4*)Ap;
    float4 ra1 = *(const float4*)(Ap + 4);
    float4 rb;
    if (tid < 128) rb = *(const float4*)Bp;

    for (int kc = 0; kc < 16; kc++) {
        __syncthreads();
        As[akq+0][alr] = ra0.x; As[akq+1][alr] = ra0.y;
        As[akq+2][alr] = ra0.z; As[akq+3][alr] = ra0.w;
        As[akq+4][alr] = ra1.x; As[akq+5][alr] = ra1.y;
        As[akq+6][alr] = ra1.z; As[akq+7][alr] = ra1.w;
        if (tid < 128) {
            Bs[bkq+0][bnl] = rb.x; Bs[bkq+1][bnl] = rb.y;
            Bs[bkq+2][bnl] = rb.z; Bs[bkq+3][bnl] = rb.w;
        }
        __syncthreads();
        if (kc < 15) {
            Ap += 16;
            ra0 = *(const float4*)Ap;
            ra1 = *(const float4*)(Ap + 4);
            if (tid < 128) { Bp += 16; rb = *(const float4*)Bp; }
        }
#pragma unroll
        for (int kk = 0; kk < 16; kk++) {
            float4 a = *(const float4*)&As[kk][tm0];
            ulonglong2 b = *(const ulonglong2*)&Bs[kk][tn0];
            float av[4] = {a.x, a.y, a.z, a.w};
#pragma unroll
            for (int i = 0; i < 4; i++) {
                ull ap = pk2(av[i], av[i]);
                fma2(acc[i][0], ap, b.x);
                fma2(acc[i][1], ap, b.y);
            }
        }
    }

    float* P = g_p1 + (size_t)blockIdx.y * (B_ * 2048);
#pragma unroll
    for (int i = 0; i < 4; i++) {
        float* Pp = P + (size_t)(tm0 + i) * 2048 + n0 + tn0;
#pragma unroll
        for (int j = 0; j < 2; j++) {
            float lo, hi; upk2(acc[i][j], lo, hi);
            Pp[2*j] = lo; Pp[2*j + 1] = hi;
        }
    }
}

// ---------------------------------------------------------------------------
// Decoder GEMM 2 (gi from weighted, split-K)
// ---------------------------------------------------------------------------
__global__ __launch_bounds__(256) void dec_gemm_gi(
    const float* __restrict__ Wih, int t_step)
{
    __shared__ __align__(16) float As[16][132];
    __shared__ __align__(16) float Bs[16][36];
    const int tid = threadIdx.x;
    const int n0 = blockIdx.x * 32;
    const int k0base = blockIdx.y * 256;
    const int tx = tid & 7, ty = tid >> 3;
    const int tm0 = ty * 4, tn0 = tx * 4;
    const int alr = tid >> 1, akq = (tid & 1) * 8;
    const int bn = n0 + (tid >> 2), bkq = (tid & 3) * 4, bnl = tid >> 2;

    const float* Ap = g_feat + ((size_t)t_step * B_ + alr) * FEAT_ + D_ + k0base + akq;
    const float* Bp = Wih + (size_t)bn * (EMB_ + 2*E_) + EMB_ + k0base + bkq;

    ull acc[4][2];
#pragma unroll
    for (int i = 0; i < 4; i++) { acc[i][0] = 0ull; acc[i][1] = 0ull; }

    float4 ra0 = *(const float4*)Ap;
    float4 ra1 = *(const float4*)(Ap + 4);
    float4 rb;
    if (tid < 128) rb = *(const float4*)Bp;

    for (int kc = 0; kc < 16; kc++) {
        __syncthreads();
        As[akq+0][alr] = ra0.x; As[akq+1][alr] = ra0.y;
        As[akq+2][alr] = ra0.z; As[akq+3][alr] = ra0.w;
        As[akq+4][alr] = ra1.x; As[akq+5][alr] = ra1.y;
        As[akq+6][alr] = ra1.z; As[akq+7][alr] = ra1.w;
        if (tid < 128) {
            Bs[bkq+0][bnl] = rb.x; Bs[bkq+1][bnl] = rb.y;
            Bs[bkq+2][bnl] = rb.z; Bs[bkq+3][bnl] = rb.w;
        }
        __syncthreads();
        if (kc < 15) {
            Ap += 16;
            ra0 = *(const float4*)Ap;
            ra1 = *(const float4*)(Ap + 4);
            if (tid < 128) { Bp += 16; rb = *(const float4*)Bp; }
        }
#pragma unroll
        for (int kk = 0; kk < 16; kk++) {
            float4 a = *(const float4*)&As[kk][tm0];
            ulonglong2 b = *(const ulonglong2*)&Bs[kk][tn0];
            float av[4] = {a.x, a.y, a.z, a.w};
#pragma unroll
            for (int i = 0; i < 4; i++) {
                ull ap = pk2(av[i], av[i]);
                fma2(acc[i][0], ap, b.x);
                fma2(acc[i][1], ap, b.y);
            }
        }
    }

    float* P = g_p2 + (size_t)blockIdx.y * (B_ * 1536);
#pragma unroll
    for (int i = 0; i < 4; i++) {
        float* Pp = P + (size_t)(tm0 + i) * 1536 + n0 + tn0;
#pragma unroll
        for (int j = 0; j < 2; j++) {
            float lo, hi; upk2(acc[i][j], lo, hi);
            Pp[2*j] = lo; Pp[2*j + 1] = hi;
        }
    }
}

// ---------------------------------------------------------------------------
// Whh transpose
// ---------------------------------------------------------------------------
__global__ void transp_k(const float* __restrict__ Wf, const float* __restrict__ Wb)
{
    const int k = blockIdx.x, dir = blockIdx.y, e = threadIdx.x;
    const float* W = dir ? Wb : Wf;
    g_WhhT[dir * (E_*E_) + k * E_ + e] = W[e * E_ + k];
}

// ---------------------------------------------------------------------------
// Encoder recurrence  (pre layout: row-major (S*B, 512) = [f | b])
// ---------------------------------------------------------------------------
__global__ __launch_bounds__(256) void enc_rnn(
    const float* __restrict__ bhh_f, const float* __restrict__ bhh_b)
{
    __shared__ __align__(16) float hsh[E_ * 4];
    const int t = threadIdx.x;
    const int dir = blockIdx.y;
    const int b0 = blockIdx.x * 4;
    const float* WT = g_WhhT + dir * (E_*E_);
    const float* pre = g_pre + dir * E_;
    const float bias = dir ? bhh_b[t] : bhh_f[t];

#pragma unroll
    for (int b = 0; b < 4; b++) hsh[t * 4 + b] = 0.f;
    __syncthreads();

    float hcur[4] = {0.f, 0.f, 0.f, 0.f};
    for (int step = 0; step < S_; step++) {
        const int s = dir ? (S_ - 1 - step) : step;
        ull a01a = 0ull, a23a = 0ull, a01b = 0ull, a23b = 0ull;
        const float* wp = WT + t;
#pragma unroll 4
        for (int k = 0; k < E_; k += 2) {
            float w0 = __ldg(wp + (size_t)k * E_);
            float w1 = __ldg(wp + (size_t)(k + 1) * E_);
            ull h01_0 = *(const ull*)&hsh[k * 4];
            ull h23_0 = *(const ull*)&hsh[k * 4 + 2];
            ull h01_1 = *(const ull*)&hsh[(k + 1) * 4];
            ull h23_1 = *(const ull*)&hsh[(k + 1) * 4 + 2];
            ull w0p = pk2(w0, w0), w1p = pk2(w1, w1);
            fma2(a01a, h01_0, w0p);
            fma2(a23a, h23_0, w0p);
            fma2(a01b, h01_1, w1p);
            fma2(a23b, h23_1, w1p);
        }
        float r0, r1, r2, r3, s0, s1, s2, s3;
        upk2(a01a, r0, r1); upk2(a23a, r2, r3);
        upk2(a01b, s0, s1); upk2(a23b, s2, s3);
        float dot[4] = {r0 + s0, r1 + s1, r2 + s2, r3 + s3};
        __syncthreads();
#pragma unroll
        for (int b = 0; b < 4; b++) {
            int row = s * B_ + b0 + b;
            float h = tanhf(pre[(size_t)row * 512 + t] + dot[b] + bias);
            hcur[b] = h;
            hsh[t * 4 + b] = h;
            g_enc_out[(size_t)row * (2*E_) + dir * E_ + t] = h;
        }
        __syncthreads();
    }
#pragma unroll
    for (int b = 0; b < 4; b++)
        g_hcat[(size_t)(b0 + b) * (2*E_) + dir * E_ + t] = hcur[b];
}

// ---------------------------------------------------------------------------
// Embedding gather -> feat[..., 1024:1280] AND g_A2 blocks 32..39
// ---------------------------------------------------------------------------
__global__ void embed_k(const int* __restrict__ trg, const float* __restrict__ table)
{
    const int m = blockIdx.x;
    const int e = threadIdx.x;
    const int t = m >> 7, b = m & (B_ - 1);
    const int tok = trg[b * T_ + t];
    float x = table[(size_t)tok * EMB_ + e];
    g_feat[(size_t)m * FEAT_ + (D_ + 2*E_) + e] = x;
    a2_write(g_A2, (size_t)m, (D_ + 2*E_) + e, x);
}

// ---------------------------------------------------------------------------
// Fused attention -> feat[..., 512:1024] AND g_A2 blocks 16..31
// ---------------------------------------------------------------------------
__global__ __launch_bounds__(512) void attn_fused_k(
    const float* __restrict__ attn_v, int t_step)
{
    __shared__ __align__(16) float qs[D_];
    __shared__ __align__(16) float vs[D_];
    __shared__ float sc[S_];
    const int b = blockIdx.x;
    const int tid = threadIdx.x;
    const int w = tid >> 5, lane = tid & 31;

    qs[tid] = g_p1[(size_t)b * 2048 + 1536 + tid]
            + g_p1[(size_t)(B_ + b) * 2048 + 1536 + tid];
    vs[tid] = attn_v[tid];
    __syncthreads();

    const float4* qp = (const float4*)qs;
    const float4* vp = (const float4*)vs;
#pragma unroll
    for (int i = 0; i < 8; i++) {
        int s = w + i * 16;
        const float4* ep = (const float4*)(g_enc_part + (size_t)(s * B_ + b) * D_);
        float acc = 0.f;
#pragma unroll
        for (int j = 0; j < 4; j++) {
            int idx = lane + 32 * j;
            float4 e = ep[idx]; float4 q = qp[idx]; float4 v = vp[idx];
            acc += tanhf(e.x + q.x) * v.x + tanhf(e.y + q.y) * v.y
                 + tanhf(e.z + q.z) * v.z + tanhf(e.w + q.w) * v.w;
        }
#pragma unroll
        for (int o = 16; o; o >>= 1) acc += __shfl_xor_sync(0xffffffffu, acc, o);
        if (lane == 0) sc[s] = acc;
    }
    __syncthreads();

    if (tid < 32) {
        float v[4]; float m = -1e30f;
#pragma unroll
        for (int i = 0; i < 4; i++) { v[i] = sc[tid + 32 * i]; m = fmaxf(m, v[i]); }
#pragma unroll
        for (int o = 16; o; o >>= 1) m = fmaxf(m, __shfl_xor_sync(0xffffffffu, m, o));
        float s = 0.f;
#pragma unroll
        for (int i = 0; i < 4; i++) { v[i] = expf(v[i] - m); s += v[i]; }
#pragma unroll
        for (int o = 16; o; o >>= 1) s += __shfl_xor_sync(0xffffffffu, s, o);
        float inv = 1.f / s;
#pragma unroll
        for (int i = 0; i < 4; i++) sc[tid + 32 * i] = v[i] * inv;
    }
    __syncthreads();

    const int e = tid;
    const float* eo = g_enc_out + (size_t)b * (2*E_) + e;
    float acc = 0.f;
#pragma unroll 4
    for (int s = 0; s < S_; s++)
        acc += sc[s] * eo[(size_t)s * B_ * (2*E_)];
    const size_t m = (size_t)t_step * B_ + b;
    g_feat[m * FEAT_ + D_ + e] = acc;
    a2_write(g_A2, m, D_ + e, acc);
}

// ---------------------------------------------------------------------------
// GRU pointwise update -> g_h, feat[...,0:512] AND g_A2 blocks 0..15
// ---------------------------------------------------------------------------
__global__ __launch_bounds__(512) void gru_k(int t_step,
    const float* __restrict__ bhh, const float* __restrict__ bih)
{
    const int b = blockIdx.x, d = threadIdx.x;
    const size_t m = (size_t)t_step * B_ + b;
    const float* p1a = g_p1 + (size_t)b * 2048;
    const float* p1b = g_p1 + (size_t)(B_ + b) * 2048;
    const float* p2a = g_p2 + (size_t)b * 1536;
    const float* p2b = g_p2 + (size_t)(B_ + b) * 1536;
    const float* ge = g_gi_emb + m * (3*D_);

    float gh_r = p1a[d] + p1b[d] + bhh[d];
    float gh_z = p1a[d + D_] + p1b[d + D_] + bhh[d + D_];
    float gh_n = p1a[d + 2*D_] + p1b[d + 2*D_] + bhh[d + 2*D_];
    float gi_r = p2a[d] + p2b[d] + bih[d];
    float gi_z = p2a[d + D_] + p2b[d + D_] + bih[d + D_];
    float gi_n = p2a[d + 2*D_] + p2b[d + 2*D_] + bih[d + 2*D_];

    float xr = gi_r + ge[d] + gh_r;
    float xz = gi_z + ge[d + D_] + gh_z;
    float gin = gi_n + ge[d + 2*D_];
    float r = 1.f / (1.f + expf(-xr));
    float z = 1.f / (1.f + expf(-xz));
    float n = tanhf(gin + r * gh_n);
    float hold = g_h[(size_t)b * D_ + d];
    float hnew = (1.f - z) * n + z * hold;
    g_h[(size_t)b * D_ + d] = hnew;
    g_feat[m * FEAT_ + d] = hnew;
    a2_write(g_A2, m, d, hnew);
}

// ---------------------------------------------------------------------------
// Row softmax over V=10000
// ---------------------------------------------------------------------------
__global__ __launch_bounds__(512) void softmax_v_k(float* __restrict__ out)
{
    const int row = blockIdx.x;
    float* p = out + (size_t)row * V_;
    const int tid = threadIdx.x, lane = tid & 31, w = tid >> 5;
    __shared__ float red[16];
    __shared__ float bc;
    float m = -1e30f;
    for (int i = tid; i < V_; i += 512) m = fmaxf(m, p[i]);
#pragma unroll
    for (int o = 16; o; o >>= 1) m = fmaxf(m, __shfl_xor_sync(0xffffffffu, m, o));
    if (lane == 0) red[w] = m;
    __syncthreads();
    if (tid == 0) {
        float mm = red[0];
        for (int i = 1; i < 16; i++) mm = fmaxf(mm, red[i]);
        bc = mm;
    }
    __syncthreads();
    m = bc;
    float s = 0.f;
    for (int i = tid; i < V_; i += 512) { float e = expf(p[i] - m); p[i] = e; s += e; }
#pragma unroll
    for (int o = 16; o; o >>= 1) s += __shfl_xor_sync(0xffffffffu, s, o);
    if (lane == 0) red[w] = s;
    __syncthreads();
    if (tid == 0) {
        float ss = 0.f;
        for (int i = 0; i < 16; i++) ss += red[i];
        bc = 1.f / ss;
    }
    __syncthreads();
    float inv = bc;
    for (int i = tid; i < V_; i += 512) p[i] *= inv;
}

// ---------------------------------------------------------------------------
// Host orchestration
// ---------------------------------------------------------------------------
extern "C" void kernel_launch(void* const* d_in, const int* in_sizes, int n_in,
                              void* d_out, int out_size)
{
    const float* src       = (const float*)d_in[0];
    const int*   trg       = (const int*)  d_in[1];
    const float* Wih_f     = (const float*)d_in[2];
    const float* Whh_f     = (const float*)d_in[3];
    const float* bih_f     = (const float*)d_in[4];
    const float* bhh_f     = (const float*)d_in[5];
    const float* Wih_b     = (const float*)d_in[6];
    const float* Whh_b     = (const float*)d_in[7];
    const float* bih_b     = (const float*)d_in[8];
    const float* bhh_b     = (const float*)d_in[9];
    const float* fcW       = (const float*)d_in[10];
    const float* fcb       = (const float*)d_in[11];
    const float* attn_W    = (const float*)d_in[12];
    const float* attn_b    = (const float*)d_in[13];
    const float* attn_v    = (const float*)d_in[14];
    const float* emb_table = (const float*)d_in[15];
    const float* gru_Wih   = (const float*)d_in[16];
    const float* gru_Whh   = (const float*)d_in[17];
    const float* gru_bih   = (const float*)d_in[18];
    const float* gru_bhh   = (const float*)d_in[19];
    const float* out_W     = (const float*)d_in[20];
    const float* out_b     = (const float*)d_in[21];
    float* out = (float*)d_out;

    // one-time stream/event setup (no device memory allocation)
    static cudaStream_t s1 = nullptr;
    static cudaEvent_t ev0, evj;
    if (!s1) {
        cudaStreamCreateWithFlags(&s1, cudaStreamNonBlocking);
        cudaEventCreateWithFlags(&ev0, cudaEventDisableTiming);
        cudaEventCreateWithFlags(&evj, cudaEventDisableTiming);
    }

    void *vp;
    cudaGetSymbolAddress(&vp, g_pre);      float* pre_p      = (float*)vp;
    cudaGetSymbolAddress(&vp, g_enc_out);  float* enc_out_p  = (float*)vp;
    cudaGetSymbolAddress(&vp, g_enc_part); float* enc_part_p = (float*)vp;
    cudaGetSymbolAddress(&vp, g_hcat);     float* hcat_p     = (float*)vp;
    cudaGetSymbolAddress(&vp, g_h);        float* h_p        = (float*)vp;
    cudaGetSymbolAddress(&vp, g_gi_emb);   float* gi_emb_p   = (float*)vp;
    cudaGetSymbolAddress(&vp, g_feat);     float* feat_p     = (float*)vp;
    cudaGetSymbolAddress(&vp, g_bpre);     float* bpre_p     = (float*)vp;
    cudaGetSymbolAddress(&vp, g_A2);       __nv_bfloat16* A2_p    = (__nv_bfloat16*)vp;
    cudaGetSymbolAddress(&vp, g_B2);       __nv_bfloat16* B2_p    = (__nv_bfloat16*)vp;
    cudaGetSymbolAddress(&vp, gA2_src);    __nv_bfloat16* A2src_p = (__nv_bfloat16*)vp;
    cudaGetSymbolAddress(&vp, gB2_pre);    __nv_bfloat16* B2pre_p = (__nv_bfloat16*)vp;
    cudaGetSymbolAddress(&vp, gA2_enc);    __nv_bfloat16* A2enc_p = (__nv_bfloat16*)vp;
    cudaGetSymbolAddress(&vp, gB2_attn);   __nv_bfloat16* B2att_p = (__nv_bfloat16*)vp;
    cudaGetSymbolAddress(&vp, gA2_emb);    __nv_bfloat16* A2emb_p = (__nv_bfloat16*)vp;
    cudaGetSymbolAddress(&vp, gB2_wih);    __nv_bfloat16* B2wih_p = (__nv_bfloat16*)vp;

    cudaFuncSetAttribute(gemm_hmma,
                         cudaFuncAttributeMaxDynamicSharedMemorySize, HMMA_SMEM);

    // fork s1 into the capture graph, run out_W split there (hidden under
    // the encoder), and record its completion for the pre-logits join.
    cudaEventRecord(ev0, 0);
    cudaStreamWaitEvent(s1, ev0, 0);
    split2_k<<<dim3(5, VPAD_), 256, 0, s1>>>(out_W, FEAT_, FEAT_, V_, B2_p);
    cudaEventRecord(evj, s1);

    // --- encoder (main stream) ---
    cat_bias_k<<<2, 256>>>(bih_f, bih_b);
    splitB2_pre_k<<<dim3(1, 512), 256>>>(Wih_f, Wih_b);
    split2_k<<<dim3(1, 16384), 256>>>(src, C_, 256, 16384, A2src_p);
    gemm_hmma<<<dim3(4, 128), 256, HMMA_SMEM>>>(A2src_p, B2pre_p, bpre_p,
                                                pre_p, 512, 512, 8, 0, 0);
    transp_k<<<dim3(256, 2), 256>>>(Whh_f, Whh_b);
    enc_rnn<<<dim3(32, 2), 256>>>(bhh_f, bhh_b);
    gemm128<<<dim3(4, 1), 256>>>(hcat_p, 2*E_, fcW, 2*E_, fcb,
                                 h_p, D_, D_, 2*E_, 1);
    split2_k<<<dim3(2, 16384), 256>>>(enc_out_p, 2*E_, 512, 16384, A2enc_p);
    split2_k<<<dim3(2, 512), 256>>>(attn_W + D_, D_ + 2*E_, 512, 512, B2att_p);
    gemm_hmma<<<dim3(4, 128), 256, HMMA_SMEM>>>(A2enc_p, B2att_p, attn_b,
                                                enc_part_p, 512, 512, 16, 0, 0);
    embed_k<<<T_ * B_, EMB_>>>(trg, emb_table);
    split2_k<<<dim3(1, 4096), 256>>>(feat_p + (D_ + 2*E_), FEAT_, 256, 4096,
                                     A2emb_p);
    split2_k<<<dim3(1, 1536), 256>>>(gru_Wih, EMB_ + 2*E_, 256, 1536, B2wih_p);
    gemm_hmma<<<dim3(12, 32), 256, HMMA_SMEM>>>(A2emb_p, B2wih_p,
                                                (const float*)nullptr,
                                                gi_emb_p, 3*D_, 3*D_, 8, 0, 0);

    // --- decoder loop (4 launches/step; R9-proven); A2 written by producers ---
    for (int t = 0; t < T_; t++) {
        dec_gemm_hq<<<dim3(64, 2), 256>>>(gru_Whh, attn_W);
        attn_fused_k<<<B_, 512>>>(attn_v, t);
        dec_gemm_gi<<<dim3(48, 2), 256>>>(gru_Wih, t);
        gru_k<<<B_, 512>>>(t, gru_bhh, gru_bih);
    }

    // --- logits GEMM (single full-chip launch) + softmax ---
    cudaStreamWaitEvent(0, evj, 0);
    gemm_hmma<<<dim3(VPAD_ / 128, 32), 256, HMMA_SMEM>>>(
        A2_p, B2_p, out_b, out, V_, V_, 40, 2, 0);
    softmax_v_k<<<T_ * B_, 512>>>(out);
}

// round 15
// speedup vs baseline: 1.2877x; 1.2073x over previous
#include <cuda_runtime.h>
#include <cuda_bf16.h>
#include <cstdint>

// ---------------------------------------------------------------------------
// Problem constants
// ---------------------------------------------------------------------------
#define S_   128
#define B_   128
#define C_   256
#define E_   256
#define D_   512
#define EMB_ 256
#define V_   10000
#define T_   32
#define FEAT_ (D_ + 2*E_ + EMB_)   // 1280
#define VPAD_ 10240

typedef unsigned long long ull;

// ---------------------------------------------------------------------------
// Scratch (__device__ globals; allocation-free)
// ---------------------------------------------------------------------------
__device__ float g_pre[S_ * B_ * 512];               // (S*B, 512) = [f|b]
__device__ float g_WhhT[2 * E_ * E_];
__device__ float g_enc_out[S_ * B_ * 2 * E_];
__device__ float g_enc_part[S_ * B_ * D_];
__device__ float g_hcat[B_ * 2 * E_];
__device__ float g_h[B_ * D_];
__device__ float g_gi_emb[T_ * B_ * 3 * D_];
__device__ float g_feat[T_ * B_ * FEAT_];
__device__ float g_p1[2 * B_ * 2048];                // split-K partials (gh|q)
__device__ float g_p2[2 * B_ * 1536];                // split-K partials (gi)
__device__ float g_bpre[512];

// factored split-bf16 operands: per row, K/32 blocks of [h(32)|l(32)]
__device__ __align__(16) __nv_bfloat16 g_A2[(size_t)(T_ * B_) * 2560];
__device__ __align__(16) __nv_bfloat16 g_B2[(size_t)VPAD_ * 2560];
__device__ __align__(16) __nv_bfloat16 gA2_src[(size_t)16384 * 512];
__device__ __align__(16) __nv_bfloat16 gB2_pre[512 * 512];
__device__ __align__(16) __nv_bfloat16 gA2_enc[(size_t)16384 * 1024];
__device__ __align__(16) __nv_bfloat16 gB2_attn[512 * 1024];
__device__ __align__(16) __nv_bfloat16 gA2_emb[4096 * 512];
__device__ __align__(16) __nv_bfloat16 gB2_wih[1536 * 512];

// ---------------------------------------------------------------------------
// helpers
// ---------------------------------------------------------------------------
__device__ __forceinline__ ull pk2(float lo, float hi) {
    ull r;
    asm("mov.b64 %0, {%1, %2};" : "=l"(r) : "f"(lo), "f"(hi));
    return r;
}
__device__ __forceinline__ void upk2(ull v, float& lo, float& hi) {
    asm("mov.b64 {%0, %1}, %2;" : "=f"(lo), "=f"(hi) : "l"(v));
}
__device__ __forceinline__ void fma2(ull& d, ull a, ull b) {
    asm("fma.rn.f32x2 %0, %1, %2, %0;" : "+l"(d) : "l"(a), "l"(b));
}
__device__ __forceinline__ uint32_t smem_u32(const void* p) {
    uint32_t a;
    asm("{ .reg .u64 t; cvta.to.shared.u64 t, %1; cvt.u32.u64 %0, t; }"
        : "=r"(a) : "l"(p));
    return a;
}

// ---------------------------------------------------------------------------
// split fp32 -> factored bf16 [h(32)|l(32)] per 32-element K block.
// ---------------------------------------------------------------------------
__global__ __launch_bounds__(256) void split2_k(
    const float* __restrict__ src, int lda, int Kf, int realRows,
    __nv_bfloat16* __restrict__ dst)
{
    const int k = blockIdx.x * 256 + threadIdx.x;
    const int r = blockIdx.y;
    float x = (r < realRows) ? src[(size_t)r * lda + k] : 0.f;
    __nv_bfloat16 h = __float2bfloat16(x);
    __nv_bfloat16 l = __float2bfloat16(x - __bfloat162float(h));
    size_t base = (size_t)r * 2 * Kf + (size_t)(k >> 5) * 64 + (k & 31);
    dst[base] = h;
    dst[base + 32] = l;
}

__global__ __launch_bounds__(256) void splitB2_pre_k(
    const float* __restrict__ Wf, const float* __restrict__ Wb)
{
    const int k = threadIdx.x;
    const int r = blockIdx.y;
    const float* W = (r < 256) ? Wf : Wb;
    float x = W[(size_t)(r & 255) * 256 + k];
    __nv_bfloat16 h = __float2bfloat16(x);
    __nv_bfloat16 l = __float2bfloat16(x - __bfloat162float(h));
    size_t base = (size_t)r * 512 + (size_t)(k >> 5) * 64 + (k & 31);
    gB2_pre[base] = h;
    gB2_pre[base + 32] = l;
}

__global__ void cat_bias_k(const float* __restrict__ a, const float* __restrict__ b)
{
    int i = blockIdx.x * 256 + threadIdx.x;
    g_bpre[i] = (i < 256) ? a[i] : b[i - 256];
}

// ---------------------------------------------------------------------------
// Factored split-bf16 HMMA GEMM (R9-proven config, interleaved LDSM/MMA)
// flags: bit0 = tanh, bit1 = (b,t) scatter for logits.
// ---------------------------------------------------------------------------
#define L3 72                          // bf16 per smem row (144 B)
#define HSTG_A (128 * L3 * 2)          // 18432 B
#define HSTG   (2 * HSTG_A)            // 36864 B (A + B)
#define HMMA_SMEM (3 * HSTG)           // 110592 B

__global__ __launch_bounds__(256, 2) void gemm_hmma(
    const __nv_bfloat16* __restrict__ A2, const __nv_bfloat16* __restrict__ B2,
    const float* __restrict__ bias, float* __restrict__ C,
    int ldc, int N, int NCH, int flags, int m_base)
{
    extern __shared__ __align__(16) char sm[];
    const uint32_t sbase = smem_u32(sm);
    const int tid = threadIdx.x, wid = tid >> 5, lane = tid & 31;
    const int m0 = m_base + blockIdx.y * 128, n0 = blockIdx.x * 128;
    const size_t ldk = (size_t)NCH * 64;

    const int lrow = tid >> 3;
    const int lcg  = tid & 7;
    const __nv_bfloat16* gA = A2 + (size_t)m0 * ldk;
    const __nv_bfloat16* gB = B2 + (size_t)n0 * ldk;

    float acc[4][4][4];
#pragma unroll
    for (int a = 0; a < 4; a++)
#pragma unroll
        for (int b = 0; b < 4; b++)
#pragma unroll
            for (int c = 0; c < 4; c++) acc[a][b][c] = 0.f;

    const int wr = wid >> 2, wc = wid & 3;
    const int wm = wr * 64, wn = wc * 32;

    auto issue_stage = [&](int c, int buf) {
        uint32_t sa = sbase + buf * HSTG;
        uint32_t sb = sa + HSTG_A;
        size_t kof = (size_t)c * 64 + lcg * 8;
#pragma unroll
        for (int i = 0; i < 4; i++) {
            int row = lrow + i * 32;
            uint32_t da = sa + (uint32_t)(row * L3 + lcg * 8) * 2;
            const void* pa = gA + (size_t)row * ldk + kof;
            asm volatile("cp.async.cg.shared.global [%0], [%1], 16;"
                         :: "r"(da), "l"(pa));
            uint32_t db = sb + (uint32_t)(row * L3 + lcg * 8) * 2;
            const void* pb = gB + (size_t)row * ldk + kof;
            asm volatile("cp.async.cg.shared.global [%0], [%1], 16;"
                         :: "r"(db), "l"(pb));
        }
        asm volatile("cp.async.commit_group;" ::: "memory");
    };

    issue_stage(0, 0);
    issue_stage(1, 1);

    int buf = 0;
    for (int c = 0; c < NCH; c++) {
        if (c + 2 < NCH) {
            int nb = buf + 2; if (nb >= 3) nb -= 3;
            issue_stage(c + 2, nb);
            asm volatile("cp.async.wait_group 2;" ::: "memory");
        } else if (c + 1 < NCH) {
            asm volatile("cp.async.wait_group 1;" ::: "memory");
        } else {
            asm volatile("cp.async.wait_group 0;" ::: "memory");
        }
        __syncthreads();

        const uint32_t sa  = sbase + buf * HSTG;
        const uint32_t sbm = sa + HSTG_A;

#pragma unroll
        for (int ks = 0; ks < 2; ks++) {
            const int acol = ks * 16 + ((lane >> 4) << 3);
            const int bcol = ks * 16 + ((lane & 8) ? 8 : 0);
            uint32_t bh[2][4], bl[2][4];
#pragma unroll
            for (int j = 0; j < 2; j++) {
                int row = wn + j * 16 + (lane & 7) + ((lane & 16) ? 8 : 0);
                uint32_t ad = sbm + (uint32_t)(row * L3 + bcol) * 2;
                asm volatile(
                    "ldmatrix.sync.aligned.m8n8.x4.shared.b16 {%0,%1,%2,%3}, [%4];"
                    : "=r"(bh[j][0]), "=r"(bh[j][1]),
                      "=r"(bh[j][2]), "=r"(bh[j][3])
                    : "r"(ad));
                asm volatile(
                    "ldmatrix.sync.aligned.m8n8.x4.shared.b16 {%0,%1,%2,%3}, [%4];"
                    : "=r"(bl[j][0]), "=r"(bl[j][1]),
                      "=r"(bl[j][2]), "=r"(bl[j][3])
                    : "r"(ad + 64));
            }
#pragma unroll
            for (int mt = 0; mt < 4; mt++) {
                int row = wm + mt * 16 + (lane & 15);
                uint32_t ah[4], al[4];
                uint32_t aad = sa + (uint32_t)(row * L3 + acol) * 2;
                asm volatile(
                    "ldmatrix.sync.aligned.m8n8.x4.shared.b16 {%0,%1,%2,%3}, [%4];"
                    : "=r"(ah[0]), "=r"(ah[1]), "=r"(ah[2]), "=r"(ah[3])
                    : "r"(aad));
                asm volatile(
                    "ldmatrix.sync.aligned.m8n8.x4.shared.b16 {%0,%1,%2,%3}, [%4];"
                    : "=r"(al[0]), "=r"(al[1]), "=r"(al[2]), "=r"(al[3])
                    : "r"(aad + 64));
#pragma unroll
                for (int nt = 0; nt < 4; nt++) {
                    uint32_t b0 = bh[nt >> 1][(nt & 1) * 2 + 0];
                    uint32_t b1 = bh[nt >> 1][(nt & 1) * 2 + 1];
                    uint32_t c0 = bl[nt >> 1][(nt & 1) * 2 + 0];
                    uint32_t c1 = bl[nt >> 1][(nt & 1) * 2 + 1];
                    asm volatile(
                        "mma.sync.aligned.m16n8k16.row.col.f32.bf16.bf16.f32 "
                        "{%0,%1,%2,%3}, {%4,%5,%6,%7}, {%8,%9}, {%0,%1,%2,%3};"
                        : "+f"(acc[mt][nt][0]), "+f"(acc[mt][nt][1]),
                          "+f"(acc[mt][nt][2]), "+f"(acc[mt][nt][3])
                        : "r"(ah[0]), "r"(ah[1]), "r"(ah[2]), "r"(ah[3]),
                          "r"(b0), "r"(b1));
                    asm volatile(
                        "mma.sync.aligned.m16n8k16.row.col.f32.bf16.bf16.f32 "
                        "{%0,%1,%2,%3}, {%4,%5,%6,%7}, {%8,%9}, {%0,%1,%2,%3};"
                        : "+f"(acc[mt][nt][0]), "+f"(acc[mt][nt][1]),
                          "+f"(acc[mt][nt][2]), "+f"(acc[mt][nt][3])
                        : "r"(al[0]), "r"(al[1]), "r"(al[2]), "r"(al[3]),
                          "r"(b0), "r"(b1));
                    asm volatile(
                        "mma.sync.aligned.m16n8k16.row.col.f32.bf16.bf16.f32 "
                        "{%0,%1,%2,%3}, {%4,%5,%6,%7}, {%8,%9}, {%0,%1,%2,%3};"
                        : "+f"(acc[mt][nt][0]), "+f"(acc[mt][nt][1]),
                          "+f"(acc[mt][nt][2]), "+f"(acc[mt][nt][3])
                        : "r"(ah[0]), "r"(ah[1]), "r"(ah[2]), "r"(ah[3]),
                          "r"(c0), "r"(c1));
                }
            }
        }
        __syncthreads();
        if (++buf == 3) buf = 0;
    }

    // epilogue
    const int qr = lane >> 2, qc = (lane & 3) * 2;
#pragma unroll
    for (int mt = 0; mt < 4; mt++) {
        int mA = m0 + wm + mt * 16 + qr;
        int mB = mA + 8;
        int rA = (flags & 2) ? ((mA & (B_ - 1)) * T_ + (mA >> 7)) : mA;
        int rB = (flags & 2) ? ((mB & (B_ - 1)) * T_ + (mB >> 7)) : mB;
        float* C0 = C + (size_t)rA * ldc;
        float* C1 = C + (size_t)rB * ldc;
#pragma unroll
        for (int nt = 0; nt < 4; nt++) {
            int n = n0 + wn + nt * 8 + qc;
            if (n < N) {
                float bia0 = bias ? bias[n] : 0.f;
                float bia1 = bias ? bias[n + 1] : 0.f;
                float v0 = acc[mt][nt][0] + bia0;
                float v1 = acc[mt][nt][1] + bia1;
                float v2 = acc[mt][nt][2] + bia0;
                float v3 = acc[mt][nt][3] + bia1;
                if (flags & 1) {
                    v0 = tanhf(v0); v1 = tanhf(v1);
                    v2 = tanhf(v2); v3 = tanhf(v3);
                }
                C0[n] = v0; C0[n + 1] = v1;
                C1[n] = v2; C1[n + 1] = v3;
            }
        }
    }
}

// ---------------------------------------------------------------------------
// f32x2 GEMM (tiny "hidden" projection only)
// ---------------------------------------------------------------------------
__global__ __launch_bounds__(256) void gemm128(
    const float* __restrict__ A, int lda,
    const float* __restrict__ B, int ldb,
    const float* __restrict__ bias,
    float* __restrict__ C, int ldc,
    int N, int K, int flags)
{
    __shared__ __align__(16) float As[16][132];
    __shared__ __align__(16) float Bs[16][132];
    const int tid = threadIdx.x;
    const int m0 = blockIdx.y * 128;
    const int n0 = blockIdx.x * 128;
    const int tx = tid & 15, ty = tid >> 4;
    const int tm0 = ty * 8, tn0 = tx * 8;
    const int lr = tid >> 2;
    const int kq = (tid & 3) * 4;

    ull acc[8][4];
#pragma unroll
    for (int i = 0; i < 8; i++)
#pragma unroll
        for (int j = 0; j < 4; j++) acc[i][j] = 0ull;

    const float* Ap0 = A + (size_t)(m0 + lr) * lda + kq;
    const float* Ap1 = A + (size_t)(m0 + lr + 64) * lda + kq;
    const int nb0 = n0 + lr, nb1 = n0 + lr + 64;
    const float* Bp0 = B + (size_t)nb0 * ldb + kq;
    const float* Bp1 = B + (size_t)nb1 * ldb + kq;
    const bool v0 = nb0 < N, v1 = nb1 < N;
    const float4 z4 = make_float4(0.f, 0.f, 0.f, 0.f);

    float4 ra0 = *(const float4*)Ap0;
    float4 ra1 = *(const float4*)Ap1;
    float4 rb0 = v0 ? *(const float4*)Bp0 : z4;
    float4 rb1 = v1 ? *(const float4*)Bp1 : z4;

    for (int k0 = 0; k0 < K; k0 += 16) {
        __syncthreads();
        As[kq+0][lr] = ra0.x; As[kq+1][lr] = ra0.y;
        As[kq+2][lr] = ra0.z; As[kq+3][lr] = ra0.w;
        As[kq+0][lr+64] = ra1.x; As[kq+1][lr+64] = ra1.y;
        As[kq+2][lr+64] = ra1.z; As[kq+3][lr+64] = ra1.w;
        Bs[kq+0][lr] = rb0.x; Bs[kq+1][lr] = rb0.y;
        Bs[kq+2][lr] = rb0.z; Bs[kq+3][lr] = rb0.w;
        Bs[kq+0][lr+64] = rb1.x; Bs[kq+1][lr+64] = rb1.y;
        Bs[kq+2][lr+64] = rb1.z; Bs[kq+3][lr+64] = rb1.w;
        __syncthreads();
        if (k0 + 16 < K) {
            Ap0 += 16; Ap1 += 16; Bp0 += 16; Bp1 += 16;
            ra0 = *(const float4*)Ap0;
            ra1 = *(const float4*)Ap1;
            rb0 = v0 ? *(const float4*)Bp0 : z4;
            rb1 = v1 ? *(const float4*)Bp1 : z4;
        }
#pragma unroll
        for (int kk = 0; kk < 16; kk++) {
            float4 af0 = *(const float4*)&As[kk][tm0];
            float4 af1 = *(const float4*)&As[kk][tm0 + 4];
            ulonglong2 b01 = *(const ulonglong2*)&Bs[kk][tn0];
            ulonglong2 b23 = *(const ulonglong2*)&Bs[kk][tn0 + 4];
            const ull bp0 = b01.x, bp1 = b01.y, bp2 = b23.x, bp3 = b23.y;
            float av[8] = {af0.x, af0.y, af0.z, af0.w,
                           af1.x, af1.y, af1.z, af1.w};
#pragma unroll
            for (int i = 0; i < 8; i++) {
                ull ap = pk2(av[i], av[i]);
                fma2(acc[i][0], ap, bp0);
                fma2(acc[i][1], ap, bp1);
                fma2(acc[i][2], ap, bp2);
                fma2(acc[i][3], ap, bp3);
            }
        }
    }

#pragma unroll
    for (int i = 0; i < 8; i++) {
        int m = m0 + tm0 + i;
        float* Cp = C + (size_t)m * ldc;
#pragma unroll
        for (int j = 0; j < 4; j++) {
            float lo, hi; upk2(acc[i][j], lo, hi);
            int n = n0 + tn0 + 2 * j;
            if (n < N) {
                float v = lo + (bias ? bias[n] : 0.f);
                if (flags & 1) v = tanhf(v);
                Cp[n] = v;
            }
            if (n + 1 < N) {
                float v = hi + (bias ? bias[n + 1] : 0.f);
                if (flags & 1) v = tanhf(v);
                Cp[n + 1] = v;
            }
        }
    }
}

// ---------------------------------------------------------------------------
// Decoder GEMM 1 (fused gh + q, split-K)
// ---------------------------------------------------------------------------
__global__ __launch_bounds__(256) void dec_gemm_hq(
    const float* __restrict__ Whh, const float* __restrict__ attnW)
{
    __shared__ __align__(16) float As[16][132];
    __shared__ __align__(16) float Bs[16][36];
    const int tid = threadIdx.x;
    const int n0 = blockIdx.x * 32;
    const int k0base = blockIdx.y * 256;
    const int tx = tid & 7, ty = tid >> 3;
    const int tm0 = ty * 4, tn0 = tx * 4;
    const int alr = tid >> 1, akq = (tid & 1) * 8;
    const int bn = n0 + (tid >> 2), bkq = (tid & 3) * 4, bnl = tid >> 2;

    const float* Ap = g_h + (size_t)alr * D_ + k0base + akq;
    const float* Bp = (bn < 1536)
        ? (Whh + (size_t)bn * D_ + k0base + bkq)
        : (attnW + (size_t)(bn - 1536) * (D_ + 2*E_) + k0base + bkq);

    ull acc[4][2];
#pragma unroll
    for (int i = 0; i < 4; i++) { acc[i][0] = 0ull; acc[i][1] = 0ull; }

    float4 ra0 = *(const float4*)Ap;
    float4 ra1 = *(const float4*)(Ap + 4);
    float4 rb;
    if (tid < 128) rb = *(const float4*)Bp;

    for (int kc = 0; kc < 16; kc++) {
        __syncthreads();
        As[akq+0][alr] = ra0.x; As[akq+1][alr] = ra0.y;
        As[akq+2][alr] = ra0.z; As[akq+3][alr] = ra0.w;
        As[akq+4][alr] = ra1.x; As[akq+5][alr] = ra1.y;
        As[akq+6][alr] = ra1.z; As[akq+7][alr] = ra1.w;
        if (tid < 128) {
            Bs[bkq+0][bnl] = rb.x; Bs[bkq+1][bnl] = rb.y;
            Bs[bkq+2][bnl] = rb.z; Bs[bkq+3][bnl] = rb.w;
        }
        __syncthreads();
        if (kc < 15) {
            Ap += 16;
            ra0 = *(const float4*)Ap;
            ra1 = *(const float4*)(Ap + 4);
            if (tid < 128) { Bp += 16; rb = *(const float4*)Bp; }
        }
#pragma unroll
        for (int kk = 0; kk < 16; kk++) {
            float4 a = *(const float4*)&As[kk][tm0];
            ulonglong2 b = *(const ulonglong2*)&Bs[kk][tn0];
            float av[4] = {a.x, a.y, a.z, a.w};
#pragma unroll
            for (int i = 0; i < 4; i++) {
                ull ap = pk2(av[i], av[i]);
                fma2(acc[i][0], ap, b.x);
                fma2(acc[i][1], ap, b.y);
            }
        }
    }

    float* P = g_p1 + (size_t)blockIdx.y * (B_ * 2048);
#pragma unroll
    for (int i = 0; i < 4; i++) {
        float* Pp = P + (size_t)(tm0 + i) * 2048 + n0 + tn0;
#pragma unroll
        for (int j = 0; j < 2; j++) {
            float lo, hi; upk2(acc[i][j], lo, hi);
            Pp[2*j] = lo; Pp[2*j + 1] = hi;
        }
    }
}

// ---------------------------------------------------------------------------
// Decoder GEMM 2 (gi from weighted, split-K)
// ---------------------------------------------------------------------------
__global__ __launch_bounds__(256) void dec_gemm_gi(
    const float* __restrict__ Wih, int t_step)
{
    __shared__ __align__(16) float As[16][132];
    __shared__ __align__(16) float Bs[16][36];
    const int tid = threadIdx.x;
    const int n0 = blockIdx.x * 32;
    const int k0base = blockIdx.y * 256;
    const int tx = tid & 7, ty = tid >> 3;
    const int tm0 = ty * 4, tn0 = tx * 4;
    const int alr = tid >> 1, akq = (tid & 1) * 8;
    const int bn = n0 + (tid >> 2), bkq = (tid & 3) * 4, bnl = tid >> 2;

    const float* Ap = g_feat + ((size_t)t_step * B_ + alr) * FEAT_ + D_ + k0base + akq;
    const float* Bp = Wih + (size_t)bn * (EMB_ + 2*E_) + EMB_ + k0base + bkq;

    ull acc[4][2];
#pragma unroll
    for (int i = 0; i < 4; i++) { acc[i][0] = 0ull; acc[i][1] = 0ull; }

    float4 ra0 = *(const float4*)Ap;
    float4 ra1 = *(const float4*)(Ap + 4);
    float4 rb;
    if (tid < 128) rb = *(const float4*)Bp;

    for (int kc = 0; kc < 16; kc++) {
        __syncthreads();
        As[akq+0][alr] = ra0.x; As[akq+1][alr] = ra0.y;
        As[akq+2][alr] = ra0.z; As[akq+3][alr] = ra0.w;
        As[akq+4][alr] = ra1.x; As[akq+5][alr] = ra1.y;
        As[akq+6][alr] = ra1.z; As[akq+7][alr] = ra1.w;
        if (tid < 128) {
            Bs[bkq+0][bnl] = rb.x; Bs[bkq+1][bnl] = rb.y;
            Bs[bkq+2][bnl] = rb.z; Bs[bkq+3][bnl] = rb.w;
        }
        __syncthreads();
        if (kc < 15) {
            Ap += 16;
            ra0 = *(const float4*)Ap;
            ra1 = *(const float4*)(Ap + 4);
            if (tid < 128) { Bp += 16; rb = *(const float4*)Bp; }
        }
#pragma unroll
        for (int kk = 0; kk < 16; kk++) {
            float4 a = *(const float4*)&As[kk][tm0];
            ulonglong2 b = *(const ulonglong2*)&Bs[kk][tn0];
            float av[4] = {a.x, a.y, a.z, a.w};
#pragma unroll
            for (int i = 0; i < 4; i++) {
                ull ap = pk2(av[i], av[i]);
                fma2(acc[i][0], ap, b.x);
                fma2(acc[i][1], ap, b.y);
            }
        }
    }

    float* P = g_p2 + (size_t)blockIdx.y * (B_ * 1536);
#pragma unroll
    for (int i = 0; i < 4; i++) {
        float* Pp = P + (size_t)(tm0 + i) * 1536 + n0 + tn0;
#pragma unroll
        for (int j = 0; j < 2; j++) {
            float lo, hi; upk2(acc[i][j], lo, hi);
            Pp[2*j] = lo; Pp[2*j + 1] = hi;
        }
    }
}

// ---------------------------------------------------------------------------
// Whh transpose
// ---------------------------------------------------------------------------
__global__ void transp_k(const float* __restrict__ Wf, const float* __restrict__ Wb)
{
    const int k = blockIdx.x, dir = blockIdx.y, e = threadIdx.x;
    const float* W = dir ? Wb : Wf;
    g_WhhT[dir * (E_*E_) + k * E_ + e] = W[e * E_ + k];
}

// ---------------------------------------------------------------------------
// Encoder recurrence v2: k in [0,128) of WhhT cached in dynamic smem.
// pre layout: row-major (S*B, 512) = [f | b]
// ---------------------------------------------------------------------------
#define ENC_SMEM ((128 * 256 + 4 * 256) * 4)   // 132 KB

__global__ __launch_bounds__(256) void enc_rnn(
    const float* __restrict__ bhh_f, const float* __restrict__ bhh_b)
{
    extern __shared__ __align__(16) float dsm[];
    float* ws  = dsm;                  // [128][256] (k-major, k<128)
    float* hsh = dsm + 128 * 256;      // [256][4]
    const int t = threadIdx.x;
    const int dir = blockIdx.y;
    const int b0 = blockIdx.x * 4;
    const float* WT = g_WhhT + dir * (E_*E_);
    const float* pre = g_pre + dir * E_;        // row stride 512
    const float bias = dir ? bhh_b[t] : bhh_f[t];

    // cache first half of WhhT (k = 0..127) into smem
    {
        const float4* src4 = (const float4*)WT;
        float4* dst4 = (float4*)ws;
        for (int i = t; i < (128 * 256) / 4; i += 256) dst4[i] = src4[i];
    }
#pragma unroll
    for (int b = 0; b < 4; b++) hsh[t * 4 + b] = 0.f;
    __syncthreads();

    float hcur[4] = {0.f, 0.f, 0.f, 0.f};
    for (int step = 0; step < S_; step++) {
        const int s = dir ? (S_ - 1 - step) : step;
        ull a01a = 0ull, a23a = 0ull, a01b = 0ull, a23b = 0ull;
        // k = 0..127 from smem
#pragma unroll 4
        for (int k = 0; k < 128; k += 2) {
            float w0 = ws[k * 256 + t];
            float w1 = ws[(k + 1) * 256 + t];
            ull h01_0 = *(const ull*)&hsh[k * 4];
            ull h23_0 = *(const ull*)&hsh[k * 4 + 2];
            ull h01_1 = *(const ull*)&hsh[(k + 1) * 4];
            ull h23_1 = *(const ull*)&hsh[(k + 1) * 4 + 2];
            ull w0p = pk2(w0, w0), w1p = pk2(w1, w1);
            fma2(a01a, h01_0, w0p);
            fma2(a23a, h23_0, w0p);
            fma2(a01b, h01_1, w1p);
            fma2(a23b, h23_1, w1p);
        }
        // k = 128..255 from L2
        const float* wp = WT + 128 * E_ + t;
#pragma unroll 4
        for (int k = 128; k < E_; k += 2) {
            float w0 = __ldg(wp);
            float w1 = __ldg(wp + E_);
            wp += 2 * E_;
            ull h01_0 = *(const ull*)&hsh[k * 4];
            ull h23_0 = *(const ull*)&hsh[k * 4 + 2];
            ull h01_1 = *(const ull*)&hsh[(k + 1) * 4];
            ull h23_1 = *(const ull*)&hsh[(k + 1) * 4 + 2];
            ull w0p = pk2(w0, w0), w1p = pk2(w1, w1);
            fma2(a01a, h01_0, w0p);
            fma2(a23a, h23_0, w0p);
            fma2(a01b, h01_1, w1p);
            fma2(a23b, h23_1, w1p);
        }
        float r0, r1, r2, r3, s0, s1, s2, s3;
        upk2(a01a, r0, r1); upk2(a23a, r2, r3);
        upk2(a01b, s0, s1); upk2(a23b, s2, s3);
        float dot[4] = {r0 + s0, r1 + s1, r2 + s2, r3 + s3};
        __syncthreads();
#pragma unroll
        for (int b = 0; b < 4; b++) {
            int row = s * B_ + b0 + b;
            float h = tanhf(pre[(size_t)row * 512 + t] + dot[b] + bias);
            hcur[b] = h;
            hsh[t * 4 + b] = h;
            g_enc_out[(size_t)row * (2*E_) + dir * E_ + t] = h;
        }
        __syncthreads();
    }
#pragma unroll
    for (int b = 0; b < 4; b++)
        g_hcat[(size_t)(b0 + b) * (2*E_) + dir * E_ + t] = hcur[b];
}

// ---------------------------------------------------------------------------
// Embedding gather -> feat[..., 1024:1280]
// ---------------------------------------------------------------------------
__global__ void embed_k(const int* __restrict__ trg, const float* __restrict__ table)
{
    const int m = blockIdx.x;
    const int e = threadIdx.x;
    const int t = m >> 7, b = m & (B_ - 1);
    const int tok = trg[b * T_ + t];
    g_feat[(size_t)m * FEAT_ + (D_ + 2*E_) + e] = table[(size_t)tok * EMB_ + e];
}

// ---------------------------------------------------------------------------
// Fused attention: q from split-K partials -> scores -> softmax -> weighted
// ---------------------------------------------------------------------------
__global__ __launch_bounds__(512) void attn_fused_k(
    const float* __restrict__ attn_v, int t_step)
{
    __shared__ __align__(16) float qs[D_];
    __shared__ __align__(16) float vs[D_];
    __shared__ float sc[S_];
    const int b = blockIdx.x;
    const int tid = threadIdx.x;
    const int w = tid >> 5, lane = tid & 31;

    qs[tid] = g_p1[(size_t)b * 2048 + 1536 + tid]
            + g_p1[(size_t)(B_ + b) * 2048 + 1536 + tid];
    vs[tid] = attn_v[tid];
    __syncthreads();

    const float4* qp = (const float4*)qs;
    const float4* vp = (const float4*)vs;
#pragma unroll
    for (int i = 0; i < 8; i++) {
        int s = w + i * 16;
        const float4* ep = (const float4*)(g_enc_part + (size_t)(s * B_ + b) * D_);
        float acc = 0.f;
#pragma unroll
        for (int j = 0; j < 4; j++) {
            int idx = lane + 32 * j;
            float4 e = ep[idx]; float4 q = qp[idx]; float4 v = vp[idx];
            acc += tanhf(e.x + q.x) * v.x + tanhf(e.y + q.y) * v.y
                 + tanhf(e.z + q.z) * v.z + tanhf(e.w + q.w) * v.w;
        }
#pragma unroll
        for (int o = 16; o; o >>= 1) acc += __shfl_xor_sync(0xffffffffu, acc, o);
        if (lane == 0) sc[s] = acc;
    }
    __syncthreads();

    if (tid < 32) {
        float v[4]; float m = -1e30f;
#pragma unroll
        for (int i = 0; i < 4; i++) { v[i] = sc[tid + 32 * i]; m = fmaxf(m, v[i]); }
#pragma unroll
        for (int o = 16; o; o >>= 1) m = fmaxf(m, __shfl_xor_sync(0xffffffffu, m, o));
        float s = 0.f;
#pragma unroll
        for (int i = 0; i < 4; i++) { v[i] = expf(v[i] - m); s += v[i]; }
#pragma unroll
        for (int o = 16; o; o >>= 1) s += __shfl_xor_sync(0xffffffffu, s, o);
        float inv = 1.f / s;
#pragma unroll
        for (int i = 0; i < 4; i++) sc[tid + 32 * i] = v[i] * inv;
    }
    __syncthreads();

    const int e = tid;
    const float* eo = g_enc_out + (size_t)b * (2*E_) + e;
    float acc = 0.f;
#pragma unroll 4
    for (int s = 0; s < S_; s++)
        acc += sc[s] * eo[(size_t)s * B_ * (2*E_)];
    g_feat[((size_t)t_step * B_ + b) * FEAT_ + D_ + e] = acc;
}

// ---------------------------------------------------------------------------
// GRU pointwise update (combines split-K partials + biases inline)
// ---------------------------------------------------------------------------
__global__ __launch_bounds__(512) void gru_k(int t_step,
    const float* __restrict__ bhh, const float* __restrict__ bih)
{
    const int b = blockIdx.x, d = threadIdx.x;
    const size_t m = (size_t)t_step * B_ + b;
    const float* p1a = g_p1 + (size_t)b * 2048;
    const float* p1b = g_p1 + (size_t)(B_ + b) * 2048;
    const float* p2a = g_p2 + (size_t)b * 1536;
    const float* p2b = g_p2 + (size_t)(B_ + b) * 1536;
    const float* ge = g_gi_emb + m * (3*D_);

    float gh_r = p1a[d] + p1b[d] + bhh[d];
    float gh_z = p1a[d + D_] + p1b[d + D_] + bhh[d + D_];
    float gh_n = p1a[d + 2*D_] + p1b[d + 2*D_] + bhh[d + 2*D_];
    float gi_r = p2a[d] + p2b[d] + bih[d];
    float gi_z = p2a[d + D_] + p2b[d + D_] + bih[d + D_];
    float gi_n = p2a[d + 2*D_] + p2b[d + 2*D_] + bih[d + 2*D_];

    float xr = gi_r + ge[d] + gh_r;
    float xz = gi_z + ge[d + D_] + gh_z;
    float gin = gi_n + ge[d + 2*D_];
    float r = 1.f / (1.f + expf(-xr));
    float z = 1.f / (1.f + expf(-xz));
    float n = tanhf(gin + r * gh_n);
    float hold = g_h[(size_t)b * D_ + d];
    float hnew = (1.f - z) * n + z * hold;
    g_h[(size_t)b * D_ + d] = hnew;
    g_feat[m * FEAT_ + d] = hnew;
}

// ---------------------------------------------------------------------------
// Row softmax over V=10000
// ---------------------------------------------------------------------------
__global__ __launch_bounds__(512) void softmax_v_k(float* __restrict__ out)
{
    const int row = blockIdx.x;
    float* p = out + (size_t)row * V_;
    const int tid = threadIdx.x, lane = tid & 31, w = tid >> 5;
    __shared__ float red[16];
    __shared__ float bc;
    float m = -1e30f;
    for (int i = tid; i < V_; i += 512) m = fmaxf(m, p[i]);
#pragma unroll
    for (int o = 16; o; o >>= 1) m = fmaxf(m, __shfl_xor_sync(0xffffffffu, m, o));
    if (lane == 0) red[w] = m;
    __syncthreads();
    if (tid == 0) {
        float mm = red[0];
        for (int i = 1; i < 16; i++) mm = fmaxf(mm, red[i]);
        bc = mm;
    }
    __syncthreads();
    m = bc;
    float s = 0.f;
    for (int i = tid; i < V_; i += 512) { float e = expf(p[i] - m); p[i] = e; s += e; }
#pragma unroll
    for (int o = 16; o; o >>= 1) s += __shfl_xor_sync(0xffffffffu, s, o);
    if (lane == 0) red[w] = s;
    __syncthreads();
    if (tid == 0) {
        float ss = 0.f;
        for (int i = 0; i < 16; i++) ss += red[i];
        bc = 1.f / ss;
    }
    __syncthreads();
    float inv = bc;
    for (int i = tid; i < V_; i += 512) p[i] *= inv;
}

// ---------------------------------------------------------------------------
// Host orchestration
// ---------------------------------------------------------------------------
extern "C" void kernel_launch(void* const* d_in, const int* in_sizes, int n_in,
                              void* d_out, int out_size)
{
    const float* src       = (const float*)d_in[0];
    const int*   trg       = (const int*)  d_in[1];
    const float* Wih_f     = (const float*)d_in[2];
    const float* Whh_f     = (const float*)d_in[3];
    const float* bih_f     = (const float*)d_in[4];
    const float* bhh_f     = (const float*)d_in[5];
    const float* Wih_b     = (const float*)d_in[6];
    const float* Whh_b     = (const float*)d_in[7];
    const float* bih_b     = (const float*)d_in[8];
    const float* bhh_b     = (const float*)d_in[9];
    const float* fcW       = (const float*)d_in[10];
    const float* fcb       = (const float*)d_in[11];
    const float* attn_W    = (const float*)d_in[12];
    const float* attn_b    = (const float*)d_in[13];
    const float* attn_v    = (const float*)d_in[14];
    const float* emb_table = (const float*)d_in[15];
    const float* gru_Wih   = (const float*)d_in[16];
    const float* gru_Whh   = (const float*)d_in[17];
    const float* gru_bih   = (const float*)d_in[18];
    const float* gru_bhh   = (const float*)d_in[19];
    const float* out_W     = (const float*)d_in[20];
    const float* out_b     = (const float*)d_in[21];
    float* out = (float*)d_out;

    // one-time stream/event setup (no device memory allocation)
    static cudaStream_t s1 = nullptr;
    static cudaEvent_t ev0, evj;
    if (!s1) {
        cudaStreamCreateWithFlags(&s1, cudaStreamNonBlocking);
        cudaEventCreateWithFlags(&ev0, cudaEventDisableTiming);
        cudaEventCreateWithFlags(&evj, cudaEventDisableTiming);
    }

    void *vp;
    cudaGetSymbolAddress(&vp, g_pre);      float* pre_p      = (float*)vp;
    cudaGetSymbolAddress(&vp, g_enc_out);  float* enc_out_p  = (float*)vp;
    cudaGetSymbolAddress(&vp, g_enc_part); float* enc_part_p = (float*)vp;
    cudaGetSymbolAddress(&vp, g_hcat);     float* hcat_p     = (float*)vp;
    cudaGetSymbolAddress(&vp, g_h);        float* h_p        = (float*)vp;
    cudaGetSymbolAddress(&vp, g_gi_emb);   float* gi_emb_p   = (float*)vp;
    cudaGetSymbolAddress(&vp, g_feat);     float* feat_p     = (float*)vp;
    cudaGetSymbolAddress(&vp, g_bpre);     float* bpre_p     = (float*)vp;
    cudaGetSymbolAddress(&vp, g_A2);       __nv_bfloat16* A2_p    = (__nv_bfloat16*)vp;
    cudaGetSymbolAddress(&vp, g_B2);       __nv_bfloat16* B2_p    = (__nv_bfloat16*)vp;
    cudaGetSymbolAddress(&vp, gA2_src);    __nv_bfloat16* A2src_p = (__nv_bfloat16*)vp;
    cudaGetSymbolAddress(&vp, gB2_pre);    __nv_bfloat16* B2pre_p = (__nv_bfloat16*)vp;
    cudaGetSymbolAddress(&vp, gA2_enc);    __nv_bfloat16* A2enc_p = (__nv_bfloat16*)vp;
    cudaGetSymbolAddress(&vp, gB2_attn);   __nv_bfloat16* B2att_p = (__nv_bfloat16*)vp;
    cudaGetSymbolAddress(&vp, gA2_emb);    __nv_bfloat16* A2emb_p = (__nv_bfloat16*)vp;
    cudaGetSymbolAddress(&vp, gB2_wih);    __nv_bfloat16* B2wih_p = (__nv_bfloat16*)vp;

    cudaFuncSetAttribute(gemm_hmma,
                         cudaFuncAttributeMaxDynamicSharedMemorySize, HMMA_SMEM);
    cudaFuncSetAttribute(enc_rnn,
                         cudaFuncAttributeMaxDynamicSharedMemorySize, ENC_SMEM);

    // fork s1 into the capture graph; out_W split hidden under the encoder
    cudaEventRecord(ev0, 0);
    cudaStreamWaitEvent(s1, ev0, 0);
    split2_k<<<dim3(5, VPAD_), 256, 0, s1>>>(out_W, FEAT_, FEAT_, V_, B2_p);
    cudaEventRecord(evj, s1);

    // --- encoder (main stream) ---
    cat_bias_k<<<2, 256>>>(bih_f, bih_b);
    splitB2_pre_k<<<dim3(1, 512), 256>>>(Wih_f, Wih_b);
    split2_k<<<dim3(1, 16384), 256>>>(src, C_, 256, 16384, A2src_p);
    gemm_hmma<<<dim3(4, 128), 256, HMMA_SMEM>>>(A2src_p, B2pre_p, bpre_p,
                                                pre_p, 512, 512, 8, 0, 0);
    transp_k<<<dim3(256, 2), 256>>>(Whh_f, Whh_b);
    enc_rnn<<<dim3(32, 2), 256, ENC_SMEM>>>(bhh_f, bhh_b);
    gemm128<<<dim3(4, 1), 256>>>(hcat_p, 2*E_, fcW, 2*E_, fcb,
                                 h_p, D_, D_, 2*E_, 1);
    split2_k<<<dim3(2, 16384), 256>>>(enc_out_p, 2*E_, 512, 16384, A2enc_p);
    split2_k<<<dim3(2, 512), 256>>>(attn_W + D_, D_ + 2*E_, 512, 512, B2att_p);
    gemm_hmma<<<dim3(4, 128), 256, HMMA_SMEM>>>(A2enc_p, B2att_p, attn_b,
                                                enc_part_p, 512, 512, 16, 0, 0);
    embed_k<<<T_ * B_, EMB_>>>(trg, emb_table);
    split2_k<<<dim3(1, 4096), 256>>>(feat_p + (D_ + 2*E_), FEAT_, 256, 4096,
                                     A2emb_p);
    split2_k<<<dim3(1, 1536), 256>>>(gru_Wih, EMB_ + 2*E_, 256, 1536, B2wih_p);
    gemm_hmma<<<dim3(12, 32), 256, HMMA_SMEM>>>(A2emb_p, B2wih_p,
                                                (const float*)nullptr,
                                                gi_emb_p, 3*D_, 3*D_, 8, 0, 0);

    // --- decoder loop (4 launches/step; R9-proven) ---
    for (int t = 0; t < T_; t++) {
        dec_gemm_hq<<<dim3(64, 2), 256>>>(gru_Whh, attn_W);
        attn_fused_k<<<B_, 512>>>(attn_v, t);
        dec_gemm_gi<<<dim3(48, 2), 256>>>(gru_Wih, t);
        gru_k<<<B_, 512>>>(t, gru_bhh, gru_bih);
    }

    // --- feat split + logits GEMM + softmax ---
    split2_k<<<dim3(5, T_ * B_), 256>>>(feat_p, FEAT_, FEAT_, T_ * B_, A2_p);
    cudaStreamWaitEvent(0, evj, 0);
    gemm_hmma<<<dim3(VPAD_ / 128, 32), 256, HMMA_SMEM>>>(
        A2_p, B2_p, out_b, out, V_, V_, 40, 2, 0);
    softmax_v_k<<<T_ * B_, 512>>>(out);
}

// round 17
// speedup vs baseline: 1.2893x; 1.0013x over previous
#include <cuda_runtime.h>
#include <cuda_bf16.h>
#include <cstdint>

// ---------------------------------------------------------------------------
// Problem constants
// ---------------------------------------------------------------------------
#define S_   128
#define B_   128
#define C_   256
#define E_   256
#define D_   512
#define EMB_ 256
#define V_   10000
#define T_   32
#define FEAT_ (D_ + 2*E_ + EMB_)   // 1280
#define VPAD_ 10240

typedef unsigned long long ull;

// ---------------------------------------------------------------------------
// Scratch (__device__ globals; allocation-free)
// ---------------------------------------------------------------------------
__device__ float g_pre[S_ * B_ * 512];               // (S*B, 512) = [f|b]
__device__ float g_WhhT[2 * E_ * E_];
__device__ float g_enc_out[S_ * B_ * 2 * E_];
__device__ float g_enc_part[S_ * B_ * D_];
__device__ float g_hcat[B_ * 2 * E_];
__device__ float g_h[B_ * D_];
__device__ float g_gi_emb[T_ * B_ * 3 * D_];
__device__ float g_feat[T_ * B_ * FEAT_];
__device__ float g_p1[2 * B_ * 2048];                // split-K partials (gh|q)
__device__ float g_p2[2 * B_ * 1536];                // split-K partials (gi)
__device__ float g_bpre[512];

// factored split-bf16 operands: per row, K/32 blocks of [h(32)|l(32)]
__device__ __align__(16) __nv_bfloat16 g_A2[(size_t)(T_ * B_) * 2560];
__device__ __align__(16) __nv_bfloat16 g_B2[(size_t)VPAD_ * 2560];
__device__ __align__(16) __nv_bfloat16 gA2_src[(size_t)16384 * 512];
__device__ __align__(16) __nv_bfloat16 gB2_pre[512 * 512];
__device__ __align__(16) __nv_bfloat16 gA2_enc[(size_t)16384 * 1024];
__device__ __align__(16) __nv_bfloat16 gB2_attn[512 * 1024];
__device__ __align__(16) __nv_bfloat16 gA2_emb[4096 * 512];
__device__ __align__(16) __nv_bfloat16 gB2_wih[1536 * 512];

// ---------------------------------------------------------------------------
// helpers
// ---------------------------------------------------------------------------
__device__ __forceinline__ ull pk2(float lo, float hi) {
    ull r;
    asm("mov.b64 %0, {%1, %2};" : "=l"(r) : "f"(lo), "f"(hi));
    return r;
}
__device__ __forceinline__ void upk2(ull v, float& lo, float& hi) {
    asm("mov.b64 {%0, %1}, %2;" : "=f"(lo), "=f"(hi) : "l"(v));
}
__device__ __forceinline__ void fma2(ull& d, ull a, ull b) {
    asm("fma.rn.f32x2 %0, %1, %2, %0;" : "+l"(d) : "l"(a), "l"(b));
}
__device__ __forceinline__ uint32_t smem_u32(const void* p) {
    uint32_t a;
    asm("{ .reg .u64 t; cvta.to.shared.u64 t, %1; cvt.u32.u64 %0, t; }"
        : "=r"(a) : "l"(p));
    return a;
}

// ---------------------------------------------------------------------------
// split fp32 -> factored bf16 [h(32)|l(32)] per 32-element K block.
// ---------------------------------------------------------------------------
__global__ __launch_bounds__(256) void split2_k(
    const float* __restrict__ src, int lda, int Kf, int realRows,
    __nv_bfloat16* __restrict__ dst)
{
    const int k = blockIdx.x * 256 + threadIdx.x;
    const int r = blockIdx.y;
    float x = (r < realRows) ? src[(size_t)r * lda + k] : 0.f;
    __nv_bfloat16 h = __float2bfloat16(x);
    __nv_bfloat16 l = __float2bfloat16(x - __bfloat162float(h));
    size_t base = (size_t)r * 2 * Kf + (size_t)(k >> 5) * 64 + (k & 31);
    dst[base] = h;
    dst[base + 32] = l;
}

__global__ __launch_bounds__(256) void splitB2_pre_k(
    const float* __restrict__ Wf, const float* __restrict__ Wb)
{
    const int k = threadIdx.x;
    const int r = blockIdx.y;
    const float* W = (r < 256) ? Wf : Wb;
    float x = W[(size_t)(r & 255) * 256 + k];
    __nv_bfloat16 h = __float2bfloat16(x);
    __nv_bfloat16 l = __float2bfloat16(x - __bfloat162float(h));
    size_t base = (size_t)r * 512 + (size_t)(k >> 5) * 64 + (k & 31);
    gB2_pre[base] = h;
    gB2_pre[base + 32] = l;
}

__global__ void cat_bias_k(const float* __restrict__ a, const float* __restrict__ b)
{
    int i = blockIdx.x * 256 + threadIdx.x;
    g_bpre[i] = (i < 256) ? a[i] : b[i - 256];
}

// ---------------------------------------------------------------------------
// Factored split-bf16 HMMA GEMM (R9-proven config, interleaved LDSM/MMA)
// flags: bit0 = tanh, bit1 = (b,t) scatter for logits.
// ---------------------------------------------------------------------------
#define L3 72                          // bf16 per smem row (144 B)
#define HSTG_A (128 * L3 * 2)          // 18432 B
#define HSTG   (2 * HSTG_A)            // 36864 B (A + B)
#define HMMA_SMEM (3 * HSTG)           // 110592 B

__global__ __launch_bounds__(256, 2) void gemm_hmma(
    const __nv_bfloat16* __restrict__ A2, const __nv_bfloat16* __restrict__ B2,
    const float* __restrict__ bias, float* __restrict__ C,
    int ldc, int N, int NCH, int flags, int m_base)
{
    extern __shared__ __align__(16) char sm[];
    const uint32_t sbase = smem_u32(sm);
    const int tid = threadIdx.x, wid = tid >> 5, lane = tid & 31;
    const int m0 = m_base + blockIdx.y * 128, n0 = blockIdx.x * 128;
    const size_t ldk = (size_t)NCH * 64;

    const int lrow = tid >> 3;
    const int lcg  = tid & 7;
    const __nv_bfloat16* gA = A2 + (size_t)m0 * ldk;
    const __nv_bfloat16* gB = B2 + (size_t)n0 * ldk;

    float acc[4][4][4];
#pragma unroll
    for (int a = 0; a < 4; a++)
#pragma unroll
        for (int b = 0; b < 4; b++)
#pragma unroll
            for (int c = 0; c < 4; c++) acc[a][b][c] = 0.f;

    const int wr = wid >> 2, wc = wid & 3;
    const int wm = wr * 64, wn = wc * 32;

    auto issue_stage = [&](int c, int buf) {
        uint32_t sa = sbase + buf * HSTG;
        uint32_t sb = sa + HSTG_A;
        size_t kof = (size_t)c * 64 + lcg * 8;
#pragma unroll
        for (int i = 0; i < 4; i++) {
            int row = lrow + i * 32;
            uint32_t da = sa + (uint32_t)(row * L3 + lcg * 8) * 2;
            const void* pa = gA + (size_t)row * ldk + kof;
            asm volatile("cp.async.cg.shared.global [%0], [%1], 16;"
                         :: "r"(da), "l"(pa));
            uint32_t db = sb + (uint32_t)(row * L3 + lcg * 8) * 2;
            const void* pb = gB + (size_t)row * ldk + kof;
            asm volatile("cp.async.cg.shared.global [%0], [%1], 16;"
                         :: "r"(db), "l"(pb));
        }
        asm volatile("cp.async.commit_group;" ::: "memory");
    };

    issue_stage(0, 0);
    issue_stage(1, 1);

    int buf = 0;
    for (int c = 0; c < NCH; c++) {
        if (c + 2 < NCH) {
            int nb = buf + 2; if (nb >= 3) nb -= 3;
            issue_stage(c + 2, nb);
            asm volatile("cp.async.wait_group 2;" ::: "memory");
        } else if (c + 1 < NCH) {
            asm volatile("cp.async.wait_group 1;" ::: "memory");
        } else {
            asm volatile("cp.async.wait_group 0;" ::: "memory");
        }
        __syncthreads();

        const uint32_t sa  = sbase + buf * HSTG;
        const uint32_t sbm = sa + HSTG_A;

#pragma unroll
        for (int ks = 0; ks < 2; ks++) {
            const int acol = ks * 16 + ((lane >> 4) << 3);
            const int bcol = ks * 16 + ((lane & 8) ? 8 : 0);
            uint32_t bh[2][4], bl[2][4];
#pragma unroll
            for (int j = 0; j < 2; j++) {
                int row = wn + j * 16 + (lane & 7) + ((lane & 16) ? 8 : 0);
                uint32_t ad = sbm + (uint32_t)(row * L3 + bcol) * 2;
                asm volatile(
                    "ldmatrix.sync.aligned.m8n8.x4.shared.b16 {%0,%1,%2,%3}, [%4];"
                    : "=r"(bh[j][0]), "=r"(bh[j][1]),
                      "=r"(bh[j][2]), "=r"(bh[j][3])
                    : "r"(ad));
                asm volatile(
                    "ldmatrix.sync.aligned.m8n8.x4.shared.b16 {%0,%1,%2,%3}, [%4];"
                    : "=r"(bl[j][0]), "=r"(bl[j][1]),
                      "=r"(bl[j][2]), "=r"(bl[j][3])
                    : "r"(ad + 64));
            }
#pragma unroll
            for (int mt = 0; mt < 4; mt++) {
                int row = wm + mt * 16 + (lane & 15);
                uint32_t ah[4], al[4];
                uint32_t aad = sa + (uint32_t)(row * L3 + acol) * 2;
                asm volatile(
                    "ldmatrix.sync.aligned.m8n8.x4.shared.b16 {%0,%1,%2,%3}, [%4];"
                    : "=r"(ah[0]), "=r"(ah[1]), "=r"(ah[2]), "=r"(ah[3])
                    : "r"(aad));
                asm volatile(
                    "ldmatrix.sync.aligned.m8n8.x4.shared.b16 {%0,%1,%2,%3}, [%4];"
                    : "=r"(al[0]), "=r"(al[1]), "=r"(al[2]), "=r"(al[3])
                    : "r"(aad + 64));
#pragma unroll
                for (int nt = 0; nt < 4; nt++) {
                    uint32_t b0 = bh[nt >> 1][(nt & 1) * 2 + 0];
                    uint32_t b1 = bh[nt >> 1][(nt & 1) * 2 + 1];
                    uint32_t c0 = bl[nt >> 1][(nt & 1) * 2 + 0];
                    uint32_t c1 = bl[nt >> 1][(nt & 1) * 2 + 1];
                    asm volatile(
                        "mma.sync.aligned.m16n8k16.row.col.f32.bf16.bf16.f32 "
                        "{%0,%1,%2,%3}, {%4,%5,%6,%7}, {%8,%9}, {%0,%1,%2,%3};"
                        : "+f"(acc[mt][nt][0]), "+f"(acc[mt][nt][1]),
                          "+f"(acc[mt][nt][2]), "+f"(acc[mt][nt][3])
                        : "r"(ah[0]), "r"(ah[1]), "r"(ah[2]), "r"(ah[3]),
                          "r"(b0), "r"(b1));
                    asm volatile(
                        "mma.sync.aligned.m16n8k16.row.col.f32.bf16.bf16.f32 "
                        "{%0,%1,%2,%3}, {%4,%5,%6,%7}, {%8,%9}, {%0,%1,%2,%3};"
                        : "+f"(acc[mt][nt][0]), "+f"(acc[mt][nt][1]),
                          "+f"(acc[mt][nt][2]), "+f"(acc[mt][nt][3])
                        : "r"(al[0]), "r"(al[1]), "r"(al[2]), "r"(al[3]),
                          "r"(b0), "r"(b1));
                    asm volatile(
                        "mma.sync.aligned.m16n8k16.row.col.f32.bf16.bf16.f32 "
                        "{%0,%1,%2,%3}, {%4,%5,%6,%7}, {%8,%9}, {%0,%1,%2,%3};"
                        : "+f"(acc[mt][nt][0]), "+f"(acc[mt][nt][1]),
                          "+f"(acc[mt][nt][2]), "+f"(acc[mt][nt][3])
                        : "r"(ah[0]), "r"(ah[1]), "r"(ah[2]), "r"(ah[3]),
                          "r"(c0), "r"(c1));
                }
            }
        }
        __syncthreads();
        if (++buf == 3) buf = 0;
    }

    // epilogue
    const int qr = lane >> 2, qc = (lane & 3) * 2;
#pragma unroll
    for (int mt = 0; mt < 4; mt++) {
        int mA = m0 + wm + mt * 16 + qr;
        int mB = mA + 8;
        int rA = (flags & 2) ? ((mA & (B_ - 1)) * T_ + (mA >> 7)) : mA;
        int rB = (flags & 2) ? ((mB & (B_ - 1)) * T_ + (mB >> 7)) : mB;
        float* C0 = C + (size_t)rA * ldc;
        float* C1 = C + (size_t)rB * ldc;
#pragma unroll
        for (int nt = 0; nt < 4; nt++) {
            int n = n0 + wn + nt * 8 + qc;
            if (n < N) {
                float bia0 = bias ? bias[n] : 0.f;
                float bia1 = bias ? bias[n + 1] : 0.f;
                float v0 = acc[mt][nt][0] + bia0;
                float v1 = acc[mt][nt][1] + bia1;
                float v2 = acc[mt][nt][2] + bia0;
                float v3 = acc[mt][nt][3] + bia1;
                if (flags & 1) {
                    v0 = tanhf(v0); v1 = tanhf(v1);
                    v2 = tanhf(v2); v3 = tanhf(v3);
                }
                C0[n] = v0; C0[n + 1] = v1;
                C1[n] = v2; C1[n + 1] = v3;
            }
        }
    }
}

// ---------------------------------------------------------------------------
// f32x2 GEMM (tiny "hidden" projection only)
// ---------------------------------------------------------------------------
__global__ __launch_bounds__(256) void gemm128(
    const float* __restrict__ A, int lda,
    const float* __restrict__ B, int ldb,
    const float* __restrict__ bias,
    float* __restrict__ C, int ldc,
    int N, int K, int flags)
{
    __shared__ __align__(16) float As[16][132];
    __shared__ __align__(16) float Bs[16][132];
    const int tid = threadIdx.x;
    const int m0 = blockIdx.y * 128;
    const int n0 = blockIdx.x * 128;
    const int tx = tid & 15, ty = tid >> 4;
    const int tm0 = ty * 8, tn0 = tx * 8;
    const int lr = tid >> 2;
    const int kq = (tid & 3) * 4;

    ull acc[8][4];
#pragma unroll
    for (int i = 0; i < 8; i++)
#pragma unroll
        for (int j = 0; j < 4; j++) acc[i][j] = 0ull;

    const float* Ap0 = A + (size_t)(m0 + lr) * lda + kq;
    const float* Ap1 = A + (size_t)(m0 + lr + 64) * lda + kq;
    const int nb0 = n0 + lr, nb1 = n0 + lr + 64;
    const float* Bp0 = B + (size_t)nb0 * ldb + kq;
    const float* Bp1 = B + (size_t)nb1 * ldb + kq;
    const bool v0 = nb0 < N, v1 = nb1 < N;
    const float4 z4 = make_float4(0.f, 0.f, 0.f, 0.f);

    float4 ra0 = *(const float4*)Ap0;
    float4 ra1 = *(const float4*)Ap1;
    float4 rb0 = v0 ? *(const float4*)Bp0 : z4;
    float4 rb1 = v1 ? *(const float4*)Bp1 : z4;

    for (int k0 = 0; k0 < K; k0 += 16) {
        __syncthreads();
        As[kq+0][lr] = ra0.x; As[kq+1][lr] = ra0.y;
        As[kq+2][lr] = ra0.z; As[kq+3][lr] = ra0.w;
        As[kq+0][lr+64] = ra1.x; As[kq+1][lr+64] = ra1.y;
        As[kq+2][lr+64] = ra1.z; As[kq+3][lr+64] = ra1.w;
        Bs[kq+0][lr] = rb0.x; Bs[kq+1][lr] = rb0.y;
        Bs[kq+2][lr] = rb0.z; Bs[kq+3][lr] = rb0.w;
        Bs[kq+0][lr+64] = rb1.x; Bs[kq+1][lr+64] = rb1.y;
        Bs[kq+2][lr+64] = rb1.z; Bs[kq+3][lr+64] = rb1.w;
        __syncthreads();
        if (k0 + 16 < K) {
            Ap0 += 16; Ap1 += 16; Bp0 += 16; Bp1 += 16;
            ra0 = *(const float4*)Ap0;
            ra1 = *(const float4*)Ap1;
            rb0 = v0 ? *(const float4*)Bp0 : z4;
            rb1 = v1 ? *(const float4*)Bp1 : z4;
        }
#pragma unroll
        for (int kk = 0; kk < 16; kk++) {
            float4 af0 = *(const float4*)&As[kk][tm0];
            float4 af1 = *(const float4*)&As[kk][tm0 + 4];
            ulonglong2 b01 = *(const ulonglong2*)&Bs[kk][tn0];
            ulonglong2 b23 = *(const ulonglong2*)&Bs[kk][tn0 + 4];
            const ull bp0 = b01.x, bp1 = b01.y, bp2 = b23.x, bp3 = b23.y;
            float av[8] = {af0.x, af0.y, af0.z, af0.w,
                           af1.x, af1.y, af1.z, af1.w};
#pragma unroll
            for (int i = 0; i < 8; i++) {
                ull ap = pk2(av[i], av[i]);
                fma2(acc[i][0], ap, bp0);
                fma2(acc[i][1], ap, bp1);
                fma2(acc[i][2], ap, bp2);
                fma2(acc[i][3], ap, bp3);
            }
        }
    }

#pragma unroll
    for (int i = 0; i < 8; i++) {
        int m = m0 + tm0 + i;
        float* Cp = C + (size_t)m * ldc;
#pragma unroll
        for (int j = 0; j < 4; j++) {
            float lo, hi; upk2(acc[i][j], lo, hi);
            int n = n0 + tn0 + 2 * j;
            if (n < N) {
                float v = lo + (bias ? bias[n] : 0.f);
                if (flags & 1) v = tanhf(v);
                Cp[n] = v;
            }
            if (n + 1 < N) {
                float v = hi + (bias ? bias[n + 1] : 0.f);
                if (flags & 1) v = tanhf(v);
                Cp[n + 1] = v;
            }
        }
    }
}

// ---------------------------------------------------------------------------
// Decoder GEMM 1 (fused gh + q, split-K)
// ---------------------------------------------------------------------------
__global__ __launch_bounds__(256) void dec_gemm_hq(
    const float* __restrict__ Whh, const float* __restrict__ attnW)
{
    __shared__ __align__(16) float As[16][132];
    __shared__ __align__(16) float Bs[16][36];
    const int tid = threadIdx.x;
    const int n0 = blockIdx.x * 32;
    const int k0base = blockIdx.y * 256;
    const int tx = tid & 7, ty = tid >> 3;
    const int tm0 = ty * 4, tn0 = tx * 4;
    const int alr = tid >> 1, akq = (tid & 1) * 8;
    const int bn = n0 + (tid >> 2), bkq = (tid & 3) * 4, bnl = tid >> 2;

    const float* Ap = g_h + (size_t)alr * D_ + k0base + akq;
    const float* Bp = (bn < 1536)
        ? (Whh + (size_t)bn * D_ + k0base + bkq)
        : (attnW + (size_t)(bn - 1536) * (D_ + 2*E_) + k0base + bkq);

    ull acc[4][2];
#pragma unroll
    for (int i = 0; i < 4; i++) { acc[i][0] = 0ull; acc[i][1] = 0ull; }

    float4 ra0 = *(const float4*)Ap;
    float4 ra1 = *(const float4*)(Ap + 4);
    float4 rb;
    if (tid < 128) rb = *(const float4*)Bp;

    for (int kc = 0; kc < 16; kc++) {
        __syncthreads();
        As[akq+0][alr] = ra0.x; As[akq+1][alr] = ra0.y;
        As[akq+2][alr] = ra0.z; As[akq+3][alr] = ra0.w;
        As[akq+4][alr] = ra1.x; As[akq+5][alr] = ra1.y;
        As[akq+6][alr] = ra1.z; As[akq+7][alr] = ra1.w;
        if (tid < 128) {
            Bs[bkq+0][bnl] = rb.x; Bs[bkq+1][bnl] = rb.y;
            Bs[bkq+2][bnl] = rb.z; Bs[bkq+3][bnl] = rb.w;
        }
        __syncthreads();
        if (kc < 15) {
            Ap += 16;
            ra0 = *(const float4*)Ap;
            ra1 = *(const float4*)(Ap + 4);
            if (tid < 128) { Bp += 16; rb = *(const float4*)Bp; }
        }
#pragma unroll
        for (int kk = 0; kk < 16; kk++) {
            float4 a = *(const float4*)&As[kk][tm0];
            ulonglong2 b = *(const ulonglong2*)&Bs[kk][tn0];
            float av[4] = {a.x, a.y, a.z, a.w};
#pragma unroll
            for (int i = 0; i < 4; i++) {
                ull ap = pk2(av[i], av[i]);
                fma2(acc[i][0], ap, b.x);
                fma2(acc[i][1], ap, b.y);
            }
        }
    }

    float* P = g_p1 + (size_t)blockIdx.y * (B_ * 2048);
#pragma unroll
    for (int i = 0; i < 4; i++) {
        float* Pp = P + (size_t)(tm0 + i) * 2048 + n0 + tn0;
#pragma unroll
        for (int j = 0; j < 2; j++) {
            float lo, hi; upk2(acc[i][j], lo, hi);
            Pp[2*j] = lo; Pp[2*j + 1] = hi;
        }
    }
}

// ---------------------------------------------------------------------------
// Decoder GEMM 2 (gi from weighted, split-K)
// ---------------------------------------------------------------------------
__global__ __launch_bounds__(256) void dec_gemm_gi(
    const float* __restrict__ Wih, int t_step)
{
    __shared__ __align__(16) float As[16][132];
    __shared__ __align__(16) float Bs[16][36];
    const int tid = threadIdx.x;
    const int n0 = blockIdx.x * 32;
    const int k0base = blockIdx.y * 256;
    const int tx = tid & 7, ty = tid >> 3;
    const int tm0 = ty * 4, tn0 = tx * 4;
    const int alr = tid >> 1, akq = (tid & 1) * 8;
    const int bn = n0 + (tid >> 2), bkq = (tid & 3) * 4, bnl = tid >> 2;

    const float* Ap = g_feat + ((size_t)t_step * B_ + alr) * FEAT_ + D_ + k0base + akq;
    const float* Bp = Wih + (size_t)bn * (EMB_ + 2*E_) + EMB_ + k0base + bkq;

    ull acc[4][2];
#pragma unroll
    for (int i = 0; i < 4; i++) { acc[i][0] = 0ull; acc[i][1] = 0ull; }

    float4 ra0 = *(const float4*)Ap;
    float4 ra1 = *(const float4*)(Ap + 4);
    float4 rb;
    if (tid < 128) rb = *(const float4*)Bp;

    for (int kc = 0; kc < 16; kc++) {
        __syncthreads();
        As[akq+0][alr] = ra0.x; As[akq+1][alr] = ra0.y;
        As[akq+2][alr] = ra0.z; As[akq+3][alr] = ra0.w;
        As[akq+4][alr] = ra1.x; As[akq+5][alr] = ra1.y;
        As[akq+6][alr] = ra1.z; As[akq+7][alr] = ra1.w;
        if (tid < 128) {
            Bs[bkq+0][bnl] = rb.x; Bs[bkq+1][bnl] = rb.y;
            Bs[bkq+2][bnl] = rb.z; Bs[bkq+3][bnl] = rb.w;
        }
        __syncthreads();
        if (kc < 15) {
            Ap += 16;
            ra0 = *(const float4*)Ap;
            ra1 = *(const float4*)(Ap + 4);
            if (tid < 128) { Bp += 16; rb = *(const float4*)Bp; }
        }
#pragma unroll
        for (int kk = 0; kk < 16; kk++) {
            float4 a = *(const float4*)&As[kk][tm0];
            ulonglong2 b = *(const ulonglong2*)&Bs[kk][tn0];
            float av[4] = {a.x, a.y, a.z, a.w};
#pragma unroll
            for (int i = 0; i < 4; i++) {
                ull ap = pk2(av[i], av[i]);
                fma2(acc[i][0], ap, b.x);
                fma2(acc[i][1], ap, b.y);
            }
        }
    }

    float* P = g_p2 + (size_t)blockIdx.y * (B_ * 1536);
#pragma unroll
    for (int i = 0; i < 4; i++) {
        float* Pp = P + (size_t)(tm0 + i) * 1536 + n0 + tn0;
#pragma unroll
        for (int j = 0; j < 2; j++) {
            float lo, hi; upk2(acc[i][j], lo, hi);
            Pp[2*j] = lo; Pp[2*j + 1] = hi;
        }
    }
}

// ---------------------------------------------------------------------------
// Whh transpose
// ---------------------------------------------------------------------------
__global__ void transp_k(const float* __restrict__ Wf, const float* __restrict__ Wb)
{
    const int k = blockIdx.x, dir = blockIdx.y, e = threadIdx.x;
    const float* W = dir ? Wb : Wf;
    g_WhhT[dir * (E_*E_) + k * E_ + e] = W[e * E_ + k];
}

// ---------------------------------------------------------------------------
// Encoder recurrence v2: k in [0,128) of WhhT cached in dynamic smem.
// pre layout: row-major (S*B, 512) = [f | b]
// ---------------------------------------------------------------------------
#define ENC_SMEM ((128 * 256 + 4 * 256) * 4)   // 132 KB

__global__ __launch_bounds__(256) void enc_rnn(
    const float* __restrict__ bhh_f, const float* __restrict__ bhh_b)
{
    extern __shared__ __align__(16) float dsm[];
    float* ws  = dsm;                  // [128][256] (k-major, k<128)
    float* hsh = dsm + 128 * 256;      // [256][4]
    const int t = threadIdx.x;
    const int dir = blockIdx.y;
    const int b0 = blockIdx.x * 4;
    const float* WT = g_WhhT + dir * (E_*E_);
    const float* pre = g_pre + dir * E_;        // row stride 512
    const float bias = dir ? bhh_b[t] : bhh_f[t];

    // cache first half of WhhT (k = 0..127) into smem
    {
        const float4* src4 = (const float4*)WT;
        float4* dst4 = (float4*)ws;
        for (int i = t; i < (128 * 256) / 4; i += 256) dst4[i] = src4[i];
    }
#pragma unroll
    for (int b = 0; b < 4; b++) hsh[t * 4 + b] = 0.f;
    __syncthreads();

    float hcur[4] = {0.f, 0.f, 0.f, 0.f};
    for (int step = 0; step < S_; step++) {
        const int s = dir ? (S_ - 1 - step) : step;
        ull a01a = 0ull, a23a = 0ull, a01b = 0ull, a23b = 0ull;
        // k = 0..127 from smem
#pragma unroll 4
        for (int k = 0; k < 128; k += 2) {
            float w0 = ws[k * 256 + t];
            float w1 = ws[(k + 1) * 256 + t];
            ull h01_0 = *(const ull*)&hsh[k * 4];
            ull h23_0 = *(const ull*)&hsh[k * 4 + 2];
            ull h01_1 = *(const ull*)&hsh[(k + 1) * 4];
            ull h23_1 = *(const ull*)&hsh[(k + 1) * 4 + 2];
            ull w0p = pk2(w0, w0), w1p = pk2(w1, w1);
            fma2(a01a, h01_0, w0p);
            fma2(a23a, h23_0, w0p);
            fma2(a01b, h01_1, w1p);
            fma2(a23b, h23_1, w1p);
        }
        // k = 128..255 from L2
        const float* wp = WT + 128 * E_ + t;
#pragma unroll 4
        for (int k = 128; k < E_; k += 2) {
            float w0 = __ldg(wp);
            float w1 = __ldg(wp + E_);
            wp += 2 * E_;
            ull h01_0 = *(const ull*)&hsh[k * 4];
            ull h23_0 = *(const ull*)&hsh[k * 4 + 2];
            ull h01_1 = *(const ull*)&hsh[(k + 1) * 4];
            ull h23_1 = *(const ull*)&hsh[(k + 1) * 4 + 2];
            ull w0p = pk2(w0, w0), w1p = pk2(w1, w1);
            fma2(a01a, h01_0, w0p);
            fma2(a23a, h23_0, w0p);
            fma2(a01b, h01_1, w1p);
            fma2(a23b, h23_1, w1p);
        }
        float r0, r1, r2, r3, s0, s1, s2, s3;
        upk2(a01a, r0, r1); upk2(a23a, r2, r3);
        upk2(a01b, s0, s1); upk2(a23b, s2, s3);
        float dot[4] = {r0 + s0, r1 + s1, r2 + s2, r3 + s3};
        __syncthreads();
#pragma unroll
        for (int b = 0; b < 4; b++) {
            int row = s * B_ + b0 + b;
            float h = tanhf(pre[(size_t)row * 512 + t] + dot[b] + bias);
            hcur[b] = h;
            hsh[t * 4 + b] = h;
            g_enc_out[(size_t)row * (2*E_) + dir * E_ + t] = h;
        }
        __syncthreads();
    }
#pragma unroll
    for (int b = 0; b < 4; b++)
        g_hcat[(size_t)(b0 + b) * (2*E_) + dir * E_ + t] = hcur[b];
}

// ---------------------------------------------------------------------------
// Embedding gather -> feat[..., 1024:1280]
// ---------------------------------------------------------------------------
__global__ void embed_k(const int* __restrict__ trg, const float* __restrict__ table)
{
    const int m = blockIdx.x;
    const int e = threadIdx.x;
    const int t = m >> 7, b = m & (B_ - 1);
    const int tok = trg[b * T_ + t];
    g_feat[(size_t)m * FEAT_ + (D_ + 2*E_) + e] = table[(size_t)tok * EMB_ + e];
}

// ---------------------------------------------------------------------------
// Fused attention: q from split-K partials -> scores -> softmax -> weighted
// ---------------------------------------------------------------------------
__global__ __launch_bounds__(512) void attn_fused_k(
    const float* __restrict__ attn_v, int t_step)
{
    __shared__ __align__(16) float qs[D_];
    __shared__ __align__(16) float vs[D_];
    __shared__ float sc[S_];
    const int b = blockIdx.x;
    const int tid = threadIdx.x;
    const int w = tid >> 5, lane = tid & 31;

    qs[tid] = g_p1[(size_t)b * 2048 + 1536 + tid]
            + g_p1[(size_t)(B_ + b) * 2048 + 1536 + tid];
    vs[tid] = attn_v[tid];
    __syncthreads();

    const float4* qp = (const float4*)qs;
    const float4* vp = (const float4*)vs;
#pragma unroll
    for (int i = 0; i < 8; i++) {
        int s = w + i * 16;
        const float4* ep = (const float4*)(g_enc_part + (size_t)(s * B_ + b) * D_);
        float acc = 0.f;
#pragma unroll
        for (int j = 0; j < 4; j++) {
            int idx = lane + 32 * j;
            float4 e = ep[idx]; float4 q = qp[idx]; float4 v = vp[idx];
            acc += tanhf(e.x + q.x) * v.x + tanhf(e.y + q.y) * v.y
                 + tanhf(e.z + q.z) * v.z + tanhf(e.w + q.w) * v.w;
        }
#pragma unroll
        for (int o = 16; o; o >>= 1) acc += __shfl_xor_sync(0xffffffffu, acc, o);
        if (lane == 0) sc[s] = acc;
    }
    __syncthreads();

    if (tid < 32) {
        float v[4]; float m = -1e30f;
#pragma unroll
        for (int i = 0; i < 4; i++) { v[i] = sc[tid + 32 * i]; m = fmaxf(m, v[i]); }
#pragma unroll
        for (int o = 16; o; o >>= 1) m = fmaxf(m, __shfl_xor_sync(0xffffffffu, m, o));
        float s = 0.f;
#pragma unroll
        for (int i = 0; i < 4; i++) { v[i] = expf(v[i] - m); s += v[i]; }
#pragma unroll
        for (int o = 16; o; o >>= 1) s += __shfl_xor_sync(0xffffffffu, s, o);
        float inv = 1.f / s;
#pragma unroll
        for (int i = 0; i < 4; i++) sc[tid + 32 * i] = v[i] * inv;
    }
    __syncthreads();

    const int e = tid;
    const float* eo = g_enc_out + (size_t)b * (2*E_) + e;
    float acc = 0.f;
#pragma unroll 4
    for (int s = 0; s < S_; s++)
        acc += sc[s] * eo[(size_t)s * B_ * (2*E_)];
    g_feat[((size_t)t_step * B_ + b) * FEAT_ + D_ + e] = acc;
}

// ---------------------------------------------------------------------------
// GRU pointwise update (combines split-K partials + biases inline)
// ---------------------------------------------------------------------------
__global__ __launch_bounds__(512) void gru_k(int t_step,
    const float* __restrict__ bhh, const float* __restrict__ bih)
{
    const int b = blockIdx.x, d = threadIdx.x;
    const size_t m = (size_t)t_step * B_ + b;
    const float* p1a = g_p1 + (size_t)b * 2048;
    const float* p1b = g_p1 + (size_t)(B_ + b) * 2048;
    const float* p2a = g_p2 + (size_t)b * 1536;
    const float* p2b = g_p2 + (size_t)(B_ + b) * 1536;
    const float* ge = g_gi_emb + m * (3*D_);

    float gh_r = p1a[d] + p1b[d] + bhh[d];
    float gh_z = p1a[d + D_] + p1b[d + D_] + bhh[d + D_];
    float gh_n = p1a[d + 2*D_] + p1b[d + 2*D_] + bhh[d + 2*D_];
    float gi_r = p2a[d] + p2b[d] + bih[d];
    float gi_z = p2a[d + D_] + p2b[d + D_] + bih[d + D_];
    float gi_n = p2a[d + 2*D_] + p2b[d + 2*D_] + bih[d + 2*D_];

    float xr = gi_r + ge[d] + gh_r;
    float xz = gi_z + ge[d + D_] + gh_z;
    float gin = gi_n + ge[d + 2*D_];
    float r = 1.f / (1.f + expf(-xr));
    float z = 1.f / (1.f + expf(-xz));
    float n = tanhf(gin + r * gh_n);
    float hold = g_h[(size_t)b * D_ + d];
    float hnew = (1.f - z) * n + z * hold;
    g_h[(size_t)b * D_ + d] = hnew;
    g_feat[m * FEAT_ + d] = hnew;
}

// ---------------------------------------------------------------------------
// Row softmax over V=10000
// ---------------------------------------------------------------------------
__global__ __launch_bounds__(512) void softmax_v_k(float* __restrict__ out)
{
    const int row = blockIdx.x;
    float* p = out + (size_t)row * V_;
    const int tid = threadIdx.x, lane = tid & 31, w = tid >> 5;
    __shared__ float red[16];
    __shared__ float bc;
    float m = -1e30f;
    for (int i = tid; i < V_; i += 512) m = fmaxf(m, p[i]);
#pragma unroll
    for (int o = 16; o; o >>= 1) m = fmaxf(m, __shfl_xor_sync(0xffffffffu, m, o));
    if (lane == 0) red[w] = m;
    __syncthreads();
    if (tid == 0) {
        float mm = red[0];
        for (int i = 1; i < 16; i++) mm = fmaxf(mm, red[i]);
        bc = mm;
    }
    __syncthreads();
    m = bc;
    float s = 0.f;
    for (int i = tid; i < V_; i += 512) { float e = expf(p[i] - m); p[i] = e; s += e; }
#pragma unroll
    for (int o = 16; o; o >>= 1) s += __shfl_xor_sync(0xffffffffu, s, o);
    if (lane == 0) red[w] = s;
    __syncthreads();
    if (tid == 0) {
        float ss = 0.f;
        for (int i = 0; i < 16; i++) ss += red[i];
        bc = 1.f / ss;
    }
    __syncthreads();
    float inv = bc;
    for (int i = tid; i < V_; i += 512) p[i] *= inv;
}

// ---------------------------------------------------------------------------
// Host orchestration
// ---------------------------------------------------------------------------
extern "C" void kernel_launch(void* const* d_in, const int* in_sizes, int n_in,
                              void* d_out, int out_size)
{
    const float* src       = (const float*)d_in[0];
    const int*   trg       = (const int*)  d_in[1];
    const float* Wih_f     = (const float*)d_in[2];
    const float* Whh_f     = (const float*)d_in[3];
    const float* bih_f     = (const float*)d_in[4];
    const float* bhh_f     = (const float*)d_in[5];
    const float* Wih_b     = (const float*)d_in[6];
    const float* Whh_b     = (const float*)d_in[7];
    const float* bih_b     = (const float*)d_in[8];
    const float* bhh_b     = (const float*)d_in[9];
    const float* fcW       = (const float*)d_in[10];
    const float* fcb       = (const float*)d_in[11];
    const float* attn_W    = (const float*)d_in[12];
    const float* attn_b    = (const float*)d_in[13];
    const float* attn_v    = (const float*)d_in[14];
    const float* emb_table = (const float*)d_in[15];
    const float* gru_Wih   = (const float*)d_in[16];
    const float* gru_Whh   = (const float*)d_in[17];
    const float* gru_bih   = (const float*)d_in[18];
    const float* gru_bhh   = (const float*)d_in[19];
    const float* out_W     = (const float*)d_in[20];
    const float* out_b     = (const float*)d_in[21];
    float* out = (float*)d_out;

    // one-time stream/event setup (no device memory allocation)
    static cudaStream_t s1 = nullptr;
    static cudaEvent_t ev0, evj;
    if (!s1) {
        cudaStreamCreateWithFlags(&s1, cudaStreamNonBlocking);
        cudaEventCreateWithFlags(&ev0, cudaEventDisableTiming);
        cudaEventCreateWithFlags(&evj, cudaEventDisableTiming);
    }

    void *vp;
    cudaGetSymbolAddress(&vp, g_pre);      float* pre_p      = (float*)vp;
    cudaGetSymbolAddress(&vp, g_enc_out);  float* enc_out_p  = (float*)vp;
    cudaGetSymbolAddress(&vp, g_enc_part); float* enc_part_p = (float*)vp;
    cudaGetSymbolAddress(&vp, g_hcat);     float* hcat_p     = (float*)vp;
    cudaGetSymbolAddress(&vp, g_h);        float* h_p        = (float*)vp;
    cudaGetSymbolAddress(&vp, g_gi_emb);   float* gi_emb_p   = (float*)vp;
    cudaGetSymbolAddress(&vp, g_feat);     float* feat_p     = (float*)vp;
    cudaGetSymbolAddress(&vp, g_bpre);     float* bpre_p     = (float*)vp;
    cudaGetSymbolAddress(&vp, g_A2);       __nv_bfloat16* A2_p    = (__nv_bfloat16*)vp;
    cudaGetSymbolAddress(&vp, g_B2);       __nv_bfloat16* B2_p    = (__nv_bfloat16*)vp;
    cudaGetSymbolAddress(&vp, gA2_src);    __nv_bfloat16* A2src_p = (__nv_bfloat16*)vp;
    cudaGetSymbolAddress(&vp, gB2_pre);    __nv_bfloat16* B2pre_p = (__nv_bfloat16*)vp;
    cudaGetSymbolAddress(&vp, gA2_enc);    __nv_bfloat16* A2enc_p = (__nv_bfloat16*)vp;
    cudaGetSymbolAddress(&vp, gB2_attn);   __nv_bfloat16* B2att_p = (__nv_bfloat16*)vp;
    cudaGetSymbolAddress(&vp, gA2_emb);    __nv_bfloat16* A2emb_p = (__nv_bfloat16*)vp;
    cudaGetSymbolAddress(&vp, gB2_wih);    __nv_bfloat16* B2wih_p = (__nv_bfloat16*)vp;

    cudaFuncSetAttribute(gemm_hmma,
                         cudaFuncAttributeMaxDynamicSharedMemorySize, HMMA_SMEM);
    cudaFuncSetAttribute(enc_rnn,
                         cudaFuncAttributeMaxDynamicSharedMemorySize, ENC_SMEM);

    // fork s1 into the capture graph; out_W split hidden under the encoder
    cudaEventRecord(ev0, 0);
    cudaStreamWaitEvent(s1, ev0, 0);
    split2_k<<<dim3(5, VPAD_), 256, 0, s1>>>(out_W, FEAT_, FEAT_, V_, B2_p);
    cudaEventRecord(evj, s1);

    // --- encoder (main stream) ---
    cat_bias_k<<<2, 256>>>(bih_f, bih_b);
    splitB2_pre_k<<<dim3(1, 512), 256>>>(Wih_f, Wih_b);
    split2_k<<<dim3(1, 16384), 256>>>(src, C_, 256, 16384, A2src_p);
    gemm_hmma<<<dim3(4, 128), 256, HMMA_SMEM>>>(A2src_p, B2pre_p, bpre_p,
                                                pre_p, 512, 512, 8, 0, 0);
    transp_k<<<dim3(256, 2), 256>>>(Whh_f, Whh_b);
    enc_rnn<<<dim3(32, 2), 256, ENC_SMEM>>>(bhh_f, bhh_b);
    gemm128<<<dim3(4, 1), 256>>>(hcat_p, 2*E_, fcW, 2*E_, fcb,
                                 h_p, D_, D_, 2*E_, 1);
    split2_k<<<dim3(2, 16384), 256>>>(enc_out_p, 2*E_, 512, 16384, A2enc_p);
    split2_k<<<dim3(2, 512), 256>>>(attn_W + D_, D_ + 2*E_, 512, 512, B2att_p);
    gemm_hmma<<<dim3(4, 128), 256, HMMA_SMEM>>>(A2enc_p, B2att_p, attn_b,
                                                enc_part_p, 512, 512, 16, 0, 0);
    embed_k<<<T_ * B_, EMB_>>>(trg, emb_table);
    split2_k<<<dim3(1, 4096), 256>>>(feat_p + (D_ + 2*E_), FEAT_, 256, 4096,
                                     A2emb_p);
    split2_k<<<dim3(1, 1536), 256>>>(gru_Wih, EMB_ + 2*E_, 256, 1536, B2wih_p);
    gemm_hmma<<<dim3(12, 32), 256, HMMA_SMEM>>>(A2emb_p, B2wih_p,
                                                (const float*)nullptr,
                                                gi_emb_p, 3*D_, 3*D_, 8, 0, 0);

    // --- decoder loop (4 launches/step; R9-proven) ---
    for (int t = 0; t < T_; t++) {
        dec_gemm_hq<<<dim3(64, 2), 256>>>(gru_Whh, attn_W);
        attn_fused_k<<<B_, 512>>>(attn_v, t);
        dec_gemm_gi<<<dim3(48, 2), 256>>>(gru_Wih, t);
        gru_k<<<B_, 512>>>(t, gru_bhh, gru_bih);
    }

    // --- feat split + logits GEMM + softmax ---
    split2_k<<<dim3(5, T_ * B_), 256>>>(feat_p, FEAT_, FEAT_, T_ * B_, A2_p);
    cudaStreamWaitEvent(0, evj, 0);
    gemm_hmma<<<dim3(VPAD_ / 128, 32), 256, HMMA_SMEM>>>(
        A2_p, B2_p, out_b, out, V_, V_, 40, 2, 0);
    softmax_v_k<<<T_ * B_, 512>>>(out);
}